// round 7
// baseline (speedup 1.0000x reference)
#include <cuda_runtime.h>
#include <cstddef>
#include <math.h>

#define B_  2
#define N_  4096
#define C_  768
#define H_  8
#define DH  96
#define M_  (B_*N_)      // 8192
#define QKVN (3*C_)      // 2304

// Scratch (static __device__ globals: allocation-free per harness rules)
__device__ float g_qkv[(size_t)M_*QKVN];   // [8192][2304] row-major
__device__ float g_ao[(size_t)M_*C_];      // [8192][768]

// HOST-side resolved DEVICE addresses of the globals above.
// CRITICAL: passing `g_qkv`/`g_ao` directly as kernel args from host code
// passes the HOST SHADOW address (silently readable via ATS on this platform,
// and full of zeros) — that was the Round-2..6 bug. Always pass these.
static float* h_qkv = nullptr;
static float* h_ao  = nullptr;

// ---------------------------------------------------------------------------
// Tiled SGEMM: 128x128 block tile, K-step 16, 256 threads, 8x8 per thread.
// Plain row-major output (stride Nw). EPI=1 adds bias.
// ---------------------------------------------------------------------------
template<int EPI>
__global__ void __launch_bounds__(256, 2) gemm_kernel(
    const float* __restrict__ A, const float* __restrict__ Bm,
    const float* __restrict__ bias, float* __restrict__ Cout,
    int K, int Nw)
{
    __shared__ float As[16][128 + 4];
    __shared__ float Bs[16][128 + 4];

    const int t  = threadIdx.x;
    const int tx = t & 15, ty = t >> 4;
    const int row0 = blockIdx.y * 128, col0 = blockIdx.x * 128;

    float acc[8][8];
    #pragma unroll
    for (int i = 0; i < 8; i++)
        #pragma unroll
        for (int j = 0; j < 8; j++) acc[i][j] = 0.f;

    const int ar = t >> 1;            // 0..127  (A tile row)
    const int ac = (t & 1) * 8;       // 0 or 8  (A tile k offset)
    const int br = t >> 5;            // 0..7    (B tile row)
    const int bc = (t & 31) * 4;      // 0..124  (B tile col)

    for (int k0 = 0; k0 < K; k0 += 16) {
        float4 a0 = *(const float4*)(A + (size_t)(row0 + ar) * K + k0 + ac);
        float4 a1 = *(const float4*)(A + (size_t)(row0 + ar) * K + k0 + ac + 4);
        As[ac + 0][ar] = a0.x; As[ac + 1][ar] = a0.y;
        As[ac + 2][ar] = a0.z; As[ac + 3][ar] = a0.w;
        As[ac + 4][ar] = a1.x; As[ac + 5][ar] = a1.y;
        As[ac + 6][ar] = a1.z; As[ac + 7][ar] = a1.w;
        *(float4*)&Bs[br][bc]     = *(const float4*)(Bm + (size_t)(k0 + br) * Nw + col0 + bc);
        *(float4*)&Bs[br + 8][bc] = *(const float4*)(Bm + (size_t)(k0 + br + 8) * Nw + col0 + bc);
        __syncthreads();

        #pragma unroll
        for (int kk = 0; kk < 16; kk++) {
            float a[8], b[8];
            #pragma unroll
            for (int i = 0; i < 8; i++) a[i] = As[kk][ty * 8 + i];
            #pragma unroll
            for (int j = 0; j < 8; j++) b[j] = Bs[kk][tx * 8 + j];
            #pragma unroll
            for (int i = 0; i < 8; i++)
                #pragma unroll
                for (int j = 0; j < 8; j++)
                    acc[i][j] = fmaf(a[i], b[j], acc[i][j]);
        }
        __syncthreads();
    }

    #pragma unroll
    for (int i = 0; i < 8; i++) {
        int m   = row0 + ty * 8 + i;
        int col = col0 + tx * 8;
        float4 v0, v1;
        if (EPI == 1) {
            v0.x = acc[i][0] + bias[col + 0]; v0.y = acc[i][1] + bias[col + 1];
            v0.z = acc[i][2] + bias[col + 2]; v0.w = acc[i][3] + bias[col + 3];
            v1.x = acc[i][4] + bias[col + 4]; v1.y = acc[i][5] + bias[col + 5];
            v1.z = acc[i][6] + bias[col + 6]; v1.w = acc[i][7] + bias[col + 7];
        } else {
            v0.x = acc[i][0]; v0.y = acc[i][1]; v0.z = acc[i][2]; v0.w = acc[i][3];
            v1.x = acc[i][4]; v1.y = acc[i][5]; v1.z = acc[i][6]; v1.w = acc[i][7];
        }
        *(float4*)&Cout[(size_t)m * Nw + col]     = v0;
        *(float4*)&Cout[(size_t)m * Nw + col + 4] = v1;
    }
}

// ---------------------------------------------------------------------------
// Flash attention, static smem < 48KB. One CTA per (b*h, 64-query tile).
// KV-tile = 32 keys; K and V time-share one 32x97 buffer.
// References g_qkv / g_ao from DEVICE code (true device addresses).
// ---------------------------------------------------------------------------
#define QP2 97
#define SSP 33

__global__ void __launch_bounds__(256) flash_kernel()
{
    __shared__ float Qs[64 * QP2];    // 24832 B
    __shared__ float KVs[32 * QP2];   // 12416 B (K, then V)
    __shared__ float Ss[64 * SSP];    //  8448 B
    __shared__ float rmax[64], rsum[64], rscale[64];   // 768 B -> 46464 B total

    const int t  = threadIdx.x;
    const int tx = t & 15, ty = t >> 4;
    const int bh = blockIdx.y;
    const int b  = bh >> 3;          // bh / H_
    const int h  = bh & 7;           // bh % H_
    const int q0 = blockIdx.x * 64;
    const float scale = 0.1020620726159657f;   // 96^-0.5

    const float* base = g_qkv + (size_t)b * N_ * QKVN + h * DH;
    const float* qb = base;             // + n*QKVN + d
    const float* kb = base + C_;
    const float* vb = base + 2 * C_;

    // Load Q tile (64 x 96)
    for (int idx = t; idx < 64 * DH; idx += 256) {
        int r = idx / DH, d = idx - r * DH;
        Qs[r * QP2 + d] = qb[(size_t)(q0 + r) * QKVN + d];
    }
    if (t < 64) { rmax[t] = -INFINITY; rsum[t] = 0.f; }

    float o[4][6];
    #pragma unroll
    for (int i = 0; i < 4; i++)
        #pragma unroll
        for (int j = 0; j < 6; j++) o[i][j] = 0.f;

    for (int kt = 0; kt < N_ / 32; kt++) {
        const int k0 = kt * 32;
        __syncthreads();   // KVs free (prev PV done), Ss free, Q/init ready

        // Load K tile (32 x 96)
        for (int idx = t; idx < 32 * DH; idx += 256) {
            int r = idx / DH, d = idx - r * DH;
            KVs[r * QP2 + d] = kb[(size_t)(k0 + r) * QKVN + d];
        }
        __syncthreads();

        // S = scale * Q K^T  (64 x 32)
        float s[4][2];
        #pragma unroll
        for (int i = 0; i < 4; i++) { s[i][0] = 0.f; s[i][1] = 0.f; }

        for (int d = 0; d < DH; d++) {
            float a[4], bb[2];
            #pragma unroll
            for (int i = 0; i < 4; i++) a[i] = Qs[(ty + 16 * i) * QP2 + d];
            #pragma unroll
            for (int j = 0; j < 2; j++) bb[j] = KVs[(tx + 16 * j) * QP2 + d];
            #pragma unroll
            for (int i = 0; i < 4; i++)
                #pragma unroll
                for (int j = 0; j < 2; j++)
                    s[i][j] = fmaf(a[i], bb[j], s[i][j]);
        }
        #pragma unroll
        for (int i = 0; i < 4; i++)
            #pragma unroll
            for (int j = 0; j < 2; j++)
                Ss[(ty + 16 * i) * SSP + (tx + 16 * j)] = s[i][j] * scale;
        __syncthreads();   // S complete; K fully consumed

        // V load (all threads) overlapped with per-row softmax (t < 64)
        for (int idx = t; idx < 32 * DH; idx += 256) {
            int r = idx / DH, d = idx - r * DH;
            KVs[r * QP2 + d] = vb[(size_t)(k0 + r) * QKVN + d];
        }
        if (t < 64) {
            float* srow = Ss + t * SSP;
            float m = rmax[t];
            #pragma unroll
            for (int c = 0; c < 32; c++) m = fmaxf(m, srow[c]);
            float sc = __expf(rmax[t] - m);
            float ssum = rsum[t] * sc;
            #pragma unroll
            for (int c = 0; c < 32; c++) {
                float p = __expf(srow[c] - m);
                srow[c] = p;
                ssum += p;
            }
            rmax[t] = m; rsum[t] = ssum; rscale[t] = sc;
        }
        __syncthreads();   // V ready, P ready, rscale ready

        // O = O*rscale + P @ V
        #pragma unroll
        for (int i = 0; i < 4; i++) {
            float sc = rscale[ty + 16 * i];
            #pragma unroll
            for (int j = 0; j < 6; j++) o[i][j] *= sc;
        }
        for (int kk = 0; kk < 32; kk++) {
            float p[4], v[6];
            #pragma unroll
            for (int i = 0; i < 4; i++) p[i] = Ss[(ty + 16 * i) * SSP + kk];
            #pragma unroll
            for (int j = 0; j < 6; j++) v[j] = KVs[kk * QP2 + (tx + 16 * j)];
            #pragma unroll
            for (int i = 0; i < 4; i++)
                #pragma unroll
                for (int j = 0; j < 6; j++)
                    o[i][j] = fmaf(p[i], v[j], o[i][j]);
        }
    }

    // Write out: g_ao[b][n][h*96 + d]
    #pragma unroll
    for (int i = 0; i < 4; i++) {
        int r = ty + 16 * i;
        int q = q0 + r;
        float inv = 1.f / rsum[r];
        #pragma unroll
        for (int j = 0; j < 6; j++) {
            int d = tx + 16 * j;
            g_ao[((size_t)b * N_ + q) * C_ + h * DH + d] = o[i][j] * inv;
        }
    }
}

// ---------------------------------------------------------------------------
// Static initializer: resolve TRUE DEVICE addresses of the globals (the fix),
// force module load, warm all kernels, and rehearse the graph path so all
// one-time driver memory transitions happen before the harness baseline.
// ---------------------------------------------------------------------------
namespace {
struct ModulePreloader {
    ModulePreloader() {
        if (cudaFree(0) != cudaSuccess) return;            // create context
        void* p = nullptr;
        if (cudaGetSymbolAddress(&p, g_qkv) != cudaSuccess) return;
        h_qkv = (float*)p;
        if (cudaGetSymbolAddress(&p, g_ao) != cudaSuccess) return;
        h_ao = (float*)p;

        dim3 g0(QKVN / 128, M_ / 128);
        dim3 g1(N_ / 64, B_ * H_);
        dim3 g2(C_ / 128, M_ / 128);

        // Plain warmups (device-resolved pointers only).
        gemm_kernel<0><<<g0, 256>>>(h_ao, h_ao, nullptr, h_qkv, C_, QKVN);
        flash_kernel<<<g1, 256>>>();
        gemm_kernel<1><<<g2, 256>>>(h_ao, h_ao, h_ao, h_qkv, C_, C_);
        if (cudaDeviceSynchronize() != cudaSuccess) return;

        // Rehearse the graph path: capture -> instantiate -> launch -> destroy.
        cudaStream_t s = nullptr;
        if (cudaStreamCreate(&s) != cudaSuccess) return;
        cudaGraph_t graph = nullptr;
        cudaGraphExec_t exec = nullptr;
        if (cudaStreamBeginCapture(s, cudaStreamCaptureModeRelaxed) == cudaSuccess) {
            gemm_kernel<0><<<g0, 256, 0, s>>>(h_ao, h_ao, nullptr, h_qkv, C_, QKVN);
            flash_kernel<<<g1, 256, 0, s>>>();
            gemm_kernel<1><<<g2, 256, 0, s>>>(h_ao, h_ao, h_ao, h_qkv, C_, C_);
            if (cudaStreamEndCapture(s, &graph) == cudaSuccess && graph) {
                if (cudaGraphInstantiate(&exec, graph, nullptr, nullptr, 0) == cudaSuccess && exec) {
                    cudaGraphLaunch(exec, s);
                    cudaStreamSynchronize(s);
                    cudaGraphExecDestroy(exec);
                }
                cudaGraphDestroy(graph);
            }
        }
        cudaStreamDestroy(s);
        cudaDeviceSynchronize();
    }
};
ModulePreloader preloader_;
}

// ---------------------------------------------------------------------------
extern "C" void kernel_launch(void* const* d_in, const int* in_sizes, int n_in,
                              void* d_out, int out_size)
{
    // Resolve inputs BY ELEMENT COUNT (all four distinct) — ordering-proof.
    const float* x      = nullptr;   // 2*4096*768   = 6291456
    const float* w_qkv  = nullptr;   // 768*2304     = 1769472
    const float* w_proj = nullptr;   // 768*768      = 589824
    const float* b_proj = nullptr;   // 768
    for (int i = 0; i < n_in; i++) {
        switch (in_sizes[i]) {
            case 6291456: x      = (const float*)d_in[i]; break;
            case 1769472: w_qkv  = (const float*)d_in[i]; break;
            case 589824:  w_proj = (const float*)d_in[i]; break;
            case 768:     b_proj = (const float*)d_in[i]; break;
            default: break;
        }
    }
    if (!x)      x      = (const float*)d_in[0];
    if (!w_qkv)  w_qkv  = (const float*)d_in[1];
    if (!w_proj) w_proj = (const float*)d_in[2];
    if (!b_proj) b_proj = (const float*)d_in[3];

    float* out = (float*)d_out;                    // [2,4096,768]

    // Safety: if preloader somehow didn't run, resolve now (host-side API,
    // not a stream op — legal under capture).
    if (!h_qkv) { void* p; cudaGetSymbolAddress(&p, g_qkv); h_qkv = (float*)p; }
    if (!h_ao)  { void* p; cudaGetSymbolAddress(&p, g_ao);  h_ao  = (float*)p; }

    // 1) QKV GEMM -> row-major g_qkv [8192][2304]  (device address!)
    {
        dim3 grid(QKVN / 128, M_ / 128);
        gemm_kernel<0><<<grid, 256>>>(x, w_qkv, nullptr, h_qkv, C_, QKVN);
    }

    // 2) Flash attention (reads g_qkv, writes g_ao internally) -> g_ao
    {
        dim3 grid(N_ / 64, B_ * H_);
        flash_kernel<<<grid, 256>>>();
    }

    // 3) Projection GEMM + bias -> d_out  (A = device address of g_ao!)
    {
        dim3 grid(C_ / 128, M_ / 128);
        gemm_kernel<1><<<grid, 256>>>(h_ao, w_proj, b_proj, out, C_, C_);
    }

    (void)out_size;
}

// round 8
// speedup vs baseline: 1.1442x; 1.1442x over previous
#include <cuda_runtime.h>
#include <cstddef>
#include <cstdint>
#include <math.h>

#define B_  2
#define N_  4096
#define C_  768
#define H_  8
#define DH  96
#define M_  (B_*N_)      // 8192
#define QKVN (3*C_)      // 2304

// Scratch (static __device__ globals: allocation-free per harness rules)
__device__ float g_qkv[(size_t)M_*QKVN];   // [8192][2304] row-major
__device__ float g_ao[(size_t)M_*C_];      // [8192][768]

// HOST-side resolved DEVICE addresses (host-shadow/ATS bug fix from R7).
static float* h_qkv = nullptr;
static float* h_ao  = nullptr;

// ---------------------------------------------------------------------------
// tf32 helpers
// ---------------------------------------------------------------------------
__device__ __forceinline__ uint32_t f2tf32(float f) {
    uint32_t u;
    asm("cvt.rna.tf32.f32 %0, %1;" : "=r"(u) : "f"(f));
    return u;
}

__device__ __forceinline__ void mma_tf32(
    float& d0, float& d1, float& d2, float& d3,
    uint32_t a0, uint32_t a1, uint32_t a2, uint32_t a3,
    uint32_t b0, uint32_t b1)
{
    asm volatile(
        "mma.sync.aligned.m16n8k8.row.col.f32.tf32.tf32.f32 "
        "{%0,%1,%2,%3}, {%4,%5,%6,%7}, {%8,%9}, {%0,%1,%2,%3};\n"
        : "+f"(d0), "+f"(d1), "+f"(d2), "+f"(d3)
        : "r"(a0), "r"(a1), "r"(a2), "r"(a3), "r"(b0), "r"(b1));
}

// ---------------------------------------------------------------------------
// tf32 tensor-core GEMM: C[M,Nw] = A[M,K] @ B[K,Nw] (+bias if EPI==1).
// CTA tile 128x128, 8 warps in 2x4 grid, warp tile 64x32 (4x4 m16n8k8 mmas).
// Double-buffered smem, K-step 8, one __syncthreads per step.
// A smem: [m][k] pitch 12 (conflict-free frag loads, 16B-aligned STS.128).
// B smem: [k][n] pitch 132.
// ---------------------------------------------------------------------------
template<int EPI>
__global__ void __launch_bounds__(256) gemm_tf32_kernel(
    const float* __restrict__ A, const float* __restrict__ Bm,
    const float* __restrict__ bias, float* __restrict__ Cout,
    int K, int Nw)
{
    __shared__ uint32_t As[2][128][12];
    __shared__ uint32_t Bs[2][8][132];

    const int t    = threadIdx.x;
    const int lane = t & 31;
    const int wid  = t >> 5;
    const int gid  = lane >> 2;     // group id 0..7
    const int tig  = lane & 3;      // thread-in-group 0..3
    const int warp_m = wid >> 2;    // 0..1
    const int warp_n = wid & 3;     // 0..3
    const int row0 = blockIdx.y * 128, col0 = blockIdx.x * 128;
    const int m_base = warp_m * 64, n_base = warp_n * 32;

    const int ar = t >> 1;          // A loader: row 0..127
    const int ac = (t & 1) * 4;     // A loader: k 0 or 4
    const int br = t >> 5;          // B loader: k 0..7
    const int bn = (t & 31) * 4;    // B loader: n 0..124

    float acc[4][4][4];
    #pragma unroll
    for (int mt = 0; mt < 4; mt++)
        #pragma unroll
        for (int nt = 0; nt < 4; nt++)
            #pragma unroll
            for (int r = 0; r < 4; r++) acc[mt][nt][r] = 0.f;

    const int KSTEPS = K / 8;

    // Prologue: load k-tile 0 into buffer 0
    {
        float4 fa = *(const float4*)(A + (size_t)(row0 + ar) * K + ac);
        float4 fb = *(const float4*)(Bm + (size_t)br * Nw + col0 + bn);
        uint4 ua = make_uint4(f2tf32(fa.x), f2tf32(fa.y), f2tf32(fa.z), f2tf32(fa.w));
        uint4 ub = make_uint4(f2tf32(fb.x), f2tf32(fb.y), f2tf32(fb.z), f2tf32(fb.w));
        *(uint4*)&As[0][ar][ac] = ua;
        *(uint4*)&Bs[0][br][bn] = ub;
    }
    __syncthreads();

    for (int kt = 0; kt < KSTEPS; kt++) {
        const int cur = kt & 1;
        float4 fa, fb;
        const bool more = (kt + 1 < KSTEPS);
        if (more) {
            int k0 = (kt + 1) * 8;
            fa = *(const float4*)(A + (size_t)(row0 + ar) * K + k0 + ac);
            fb = *(const float4*)(Bm + (size_t)(k0 + br) * Nw + col0 + bn);
        }

        // Preload B fragments for this warp (4 n-tiles x 2 regs)
        uint32_t bf[4][2];
        #pragma unroll
        for (int nt = 0; nt < 4; nt++) {
            int n = n_base + nt * 8 + gid;
            bf[nt][0] = Bs[cur][tig][n];
            bf[nt][1] = Bs[cur][tig + 4][n];
        }
        #pragma unroll
        for (int mt = 0; mt < 4; mt++) {
            int mb = m_base + mt * 16;
            uint32_t a0 = As[cur][mb + gid][tig];
            uint32_t a1 = As[cur][mb + gid + 8][tig];
            uint32_t a2 = As[cur][mb + gid][tig + 4];
            uint32_t a3 = As[cur][mb + gid + 8][tig + 4];
            #pragma unroll
            for (int nt = 0; nt < 4; nt++)
                mma_tf32(acc[mt][nt][0], acc[mt][nt][1], acc[mt][nt][2], acc[mt][nt][3],
                         a0, a1, a2, a3, bf[nt][0], bf[nt][1]);
        }

        if (more) {
            uint4 ua = make_uint4(f2tf32(fa.x), f2tf32(fa.y), f2tf32(fa.z), f2tf32(fa.w));
            uint4 ub = make_uint4(f2tf32(fb.x), f2tf32(fb.y), f2tf32(fb.z), f2tf32(fb.w));
            *(uint4*)&As[cur ^ 1][ar][ac] = ua;
            *(uint4*)&Bs[cur ^ 1][br][bn] = ub;
        }
        __syncthreads();
    }

    // Epilogue: acc layout: c0:(r=gid, c=2*tig), c1:(r, c+1), c2:(r+8, c), c3:(r+8, c+1)
    #pragma unroll
    for (int mt = 0; mt < 4; mt++) {
        #pragma unroll
        for (int nt = 0; nt < 4; nt++) {
            int r0 = row0 + m_base + mt * 16 + gid;
            int c0 = col0 + n_base + nt * 8 + 2 * tig;
            float2 v01, v23;
            if (EPI == 1) {
                float bx = bias[c0], by = bias[c0 + 1];
                v01 = make_float2(acc[mt][nt][0] + bx, acc[mt][nt][1] + by);
                v23 = make_float2(acc[mt][nt][2] + bx, acc[mt][nt][3] + by);
            } else {
                v01 = make_float2(acc[mt][nt][0], acc[mt][nt][1]);
                v23 = make_float2(acc[mt][nt][2], acc[mt][nt][3]);
            }
            *(float2*)&Cout[(size_t)r0 * Nw + c0]       = v01;
            *(float2*)&Cout[(size_t)(r0 + 8) * Nw + c0] = v23;
        }
    }
}

// ---------------------------------------------------------------------------
// Flash attention (fp32, dynamic smem 68864B). One CTA per (b*h, 64-q tile).
// KV tile 64 keys; K and V time-share one 64x97 buffer.
// Thread (tx=t&15, ty=t>>4): S rows ty+16i (i<4), S cols tx+16j (j<4),
// O cols tx+16j (j<6). Softmax: 4 threads/row (r=t&63, seg=t>>6, 16 cols).
// ---------------------------------------------------------------------------
#define FL_QP   97
#define FL_SP   65
#define FL_QS   0
#define FL_KV   (64*FL_QP)            // 6208
#define FL_SS   (FL_KV + 64*FL_QP)    // 12416
#define FL_PMAX (FL_SS + 64*FL_SP)    // 16576
#define FL_PSUM (FL_PMAX + 256)       // 16832
#define FL_RMAX (FL_PSUM + 256)       // 17088
#define FL_RSUM (FL_RMAX + 64)        // 17152
#define FLASH_SMEM ((FL_RSUM + 64) * 4)   // 68864 bytes

__global__ void __launch_bounds__(256) flash_kernel()
{
    extern __shared__ float sm[];
    float* Qs   = sm + FL_QS;
    float* KV   = sm + FL_KV;
    float* Ss   = sm + FL_SS;
    float* pmax = sm + FL_PMAX;
    float* psum = sm + FL_PSUM;
    float* rmax = sm + FL_RMAX;
    float* rsum = sm + FL_RSUM;

    const int t  = threadIdx.x;
    const int tx = t & 15, ty = t >> 4;
    const int r   = t & 63;        // softmax row
    const int seg = t >> 6;        // softmax col segment (0..3)
    const int bh = blockIdx.y;
    const int b  = bh >> 3;
    const int h  = bh & 7;
    const int q0 = blockIdx.x * 64;
    const float scale = 0.1020620726159657f;   // 96^-0.5

    const float* base = g_qkv + (size_t)b * N_ * QKVN + h * DH;
    const float* qb = base;
    const float* kb = base + C_;
    const float* vb = base + 2 * C_;

    // Load Q tile (64 x 96)
    for (int idx = t; idx < 64 * DH; idx += 256) {
        int rr = idx / DH, d = idx - rr * DH;
        Qs[rr * FL_QP + d] = qb[(size_t)(q0 + rr) * QKVN + d];
    }
    if (t < 64) { rmax[t] = -INFINITY; rsum[t] = 0.f; }

    float o[4][6];
    #pragma unroll
    for (int i = 0; i < 4; i++)
        #pragma unroll
        for (int j = 0; j < 6; j++) o[i][j] = 0.f;

    for (int kt = 0; kt < N_ / 64; kt++) {
        const int k0 = kt * 64;
        __syncthreads();   // sync0: prev Ss/KV consumed; rmax/rsum stable

        // Snapshot running maxima BEFORE any update this iteration
        float m_old_pv[4];
        #pragma unroll
        for (int i = 0; i < 4; i++) m_old_pv[i] = rmax[ty + 16 * i];
        const float m_old_sm = rmax[r];

        // Load K tile (64 x 96)
        for (int idx = t; idx < 64 * DH; idx += 256) {
            int rr = idx / DH, d = idx - rr * DH;
            KV[rr * FL_QP + d] = kb[(size_t)(k0 + rr) * QKVN + d];
        }
        __syncthreads();   // sync1: K ready, rmax snapshots taken

        // S = scale * Q K^T  (64 x 64), 4x4 per thread
        float s[4][4];
        #pragma unroll
        for (int i = 0; i < 4; i++)
            #pragma unroll
            for (int j = 0; j < 4; j++) s[i][j] = 0.f;

        #pragma unroll 4
        for (int d = 0; d < DH; d++) {
            float a[4], bb[4];
            #pragma unroll
            for (int i = 0; i < 4; i++) a[i] = Qs[(ty + 16 * i) * FL_QP + d];
            #pragma unroll
            for (int j = 0; j < 4; j++) bb[j] = KV[(tx + 16 * j) * FL_QP + d];
            #pragma unroll
            for (int i = 0; i < 4; i++)
                #pragma unroll
                for (int j = 0; j < 4; j++)
                    s[i][j] = fmaf(a[i], bb[j], s[i][j]);
        }
        #pragma unroll
        for (int i = 0; i < 4; i++)
            #pragma unroll
            for (int j = 0; j < 4; j++)
                Ss[(ty + 16 * i) * FL_SP + (tx + 16 * j)] = s[i][j] * scale;
        __syncthreads();   // sync2: S ready; K fully consumed

        // Softmax partial max (keep the 16 values in registers for exp)
        float sv[16];
        float lm = -INFINITY;
        {
            const float* srow = Ss + r * FL_SP + seg * 16;
            #pragma unroll
            for (int c = 0; c < 16; c++) { sv[c] = srow[c]; lm = fmaxf(lm, sv[c]); }
        }
        pmax[seg * 64 + r] = lm;

        // Overlap: V load (KV buffer free of K reads after sync2)
        for (int idx = t; idx < 64 * DH; idx += 256) {
            int rr = idx / DH, d = idx - rr * DH;
            KV[rr * FL_QP + d] = vb[(size_t)(k0 + rr) * QKVN + d];
        }
        __syncthreads();   // sync3a: pmax ready

        // Softmax: new row max, exp in place, partial sum
        const float m_new_sm = fmaxf(fmaxf(fmaxf(pmax[r], pmax[64 + r]),
                                           fmaxf(pmax[128 + r], pmax[192 + r])), m_old_sm);
        {
            float lsum = 0.f;
            float* srow = Ss + r * FL_SP + seg * 16;
            #pragma unroll
            for (int c = 0; c < 16; c++) {
                float p = __expf(sv[c] - m_new_sm);
                srow[c] = p;
                lsum += p;
            }
            psum[seg * 64 + r] = lsum;
        }

        // PV-role: rescale accumulators using locally recomputed factors
        #pragma unroll
        for (int i = 0; i < 4; i++) {
            int rr = ty + 16 * i;
            float mn = fmaxf(fmaxf(fmaxf(pmax[rr], pmax[64 + rr]),
                                   fmaxf(pmax[128 + rr], pmax[192 + rr])), m_old_pv[i]);
            float sc = __expf(m_old_pv[i] - mn);
            #pragma unroll
            for (int j = 0; j < 6; j++) o[i][j] *= sc;
        }
        __syncthreads();   // sync3b: exp'd S + psum + V all ready

        // Running sum/max update (one thread per row to avoid RMW race)
        if (seg == 0) {
            rsum[r] = rsum[r] * __expf(m_old_sm - m_new_sm)
                    + psum[r] + psum[64 + r] + psum[128 + r] + psum[192 + r];
            rmax[r] = m_new_sm;
        }

        // O += P @ V
        #pragma unroll 2
        for (int kk = 0; kk < 64; kk++) {
            float p[4], v[6];
            #pragma unroll
            for (int i = 0; i < 4; i++) p[i] = Ss[(ty + 16 * i) * FL_SP + kk];
            #pragma unroll
            for (int j = 0; j < 6; j++) v[j] = KV[kk * FL_QP + (tx + 16 * j)];
            #pragma unroll
            for (int i = 0; i < 4; i++)
                #pragma unroll
                for (int j = 0; j < 6; j++)
                    o[i][j] = fmaf(p[i], v[j], o[i][j]);
        }
    }
    __syncthreads();   // final rsum stable

    #pragma unroll
    for (int i = 0; i < 4; i++) {
        int rr = ty + 16 * i;
        int q = q0 + rr;
        float inv = 1.f / rsum[rr];
        #pragma unroll
        for (int j = 0; j < 6; j++) {
            int d = tx + 16 * j;
            g_ao[((size_t)b * N_ + q) * C_ + h * DH + d] = o[i][j] * inv;
        }
    }
}

// ---------------------------------------------------------------------------
// Static initializer: resolve device addresses, set flash smem attribute,
// warm all kernels, and rehearse the graph path pre-main.
// ---------------------------------------------------------------------------
namespace {
struct ModulePreloader {
    ModulePreloader() {
        if (cudaFree(0) != cudaSuccess) return;
        void* p = nullptr;
        if (cudaGetSymbolAddress(&p, g_qkv) != cudaSuccess) return;
        h_qkv = (float*)p;
        if (cudaGetSymbolAddress(&p, g_ao) != cudaSuccess) return;
        h_ao = (float*)p;

        cudaFuncSetAttribute(flash_kernel,
                             cudaFuncAttributeMaxDynamicSharedMemorySize,
                             FLASH_SMEM);

        dim3 g0(QKVN / 128, M_ / 128);
        dim3 g1(N_ / 64, B_ * H_);
        dim3 g2(C_ / 128, M_ / 128);

        gemm_tf32_kernel<0><<<g0, 256>>>(h_ao, h_ao, nullptr, h_qkv, C_, QKVN);
        flash_kernel<<<g1, 256, FLASH_SMEM>>>();
        gemm_tf32_kernel<1><<<g2, 256>>>(h_ao, h_ao, h_ao, h_qkv, C_, C_);
        if (cudaDeviceSynchronize() != cudaSuccess) return;

        cudaStream_t s = nullptr;
        if (cudaStreamCreate(&s) != cudaSuccess) return;
        cudaGraph_t graph = nullptr;
        cudaGraphExec_t exec = nullptr;
        if (cudaStreamBeginCapture(s, cudaStreamCaptureModeRelaxed) == cudaSuccess) {
            gemm_tf32_kernel<0><<<g0, 256, 0, s>>>(h_ao, h_ao, nullptr, h_qkv, C_, QKVN);
            flash_kernel<<<g1, 256, FLASH_SMEM, s>>>();
            gemm_tf32_kernel<1><<<g2, 256, 0, s>>>(h_ao, h_ao, h_ao, h_qkv, C_, C_);
            if (cudaStreamEndCapture(s, &graph) == cudaSuccess && graph) {
                if (cudaGraphInstantiate(&exec, graph, nullptr, nullptr, 0) == cudaSuccess && exec) {
                    cudaGraphLaunch(exec, s);
                    cudaStreamSynchronize(s);
                    cudaGraphExecDestroy(exec);
                }
                cudaGraphDestroy(graph);
            }
        }
        cudaStreamDestroy(s);
        cudaDeviceSynchronize();
    }
};
ModulePreloader preloader_;
}

// ---------------------------------------------------------------------------
extern "C" void kernel_launch(void* const* d_in, const int* in_sizes, int n_in,
                              void* d_out, int out_size)
{
    const float* x      = nullptr;   // 6291456
    const float* w_qkv  = nullptr;   // 1769472
    const float* w_proj = nullptr;   // 589824
    const float* b_proj = nullptr;   // 768
    for (int i = 0; i < n_in; i++) {
        switch (in_sizes[i]) {
            case 6291456: x      = (const float*)d_in[i]; break;
            case 1769472: w_qkv  = (const float*)d_in[i]; break;
            case 589824:  w_proj = (const float*)d_in[i]; break;
            case 768:     b_proj = (const float*)d_in[i]; break;
            default: break;
        }
    }
    if (!x)      x      = (const float*)d_in[0];
    if (!w_qkv)  w_qkv  = (const float*)d_in[1];
    if (!w_proj) w_proj = (const float*)d_in[2];
    if (!b_proj) b_proj = (const float*)d_in[3];

    float* out = (float*)d_out;

    if (!h_qkv) { void* p; cudaGetSymbolAddress(&p, g_qkv); h_qkv = (float*)p; }
    if (!h_ao)  { void* p; cudaGetSymbolAddress(&p, g_ao);  h_ao  = (float*)p; }

    // 1) QKV GEMM (tf32 tensor cores) -> g_qkv [8192][2304]
    {
        dim3 grid(QKVN / 128, M_ / 128);
        gemm_tf32_kernel<0><<<grid, 256>>>(x, w_qkv, nullptr, h_qkv, C_, QKVN);
    }

    // 2) Flash attention (fp32) -> g_ao
    {
        dim3 grid(N_ / 64, B_ * H_);
        flash_kernel<<<grid, 256, FLASH_SMEM>>>();
    }

    // 3) Projection GEMM + bias (tf32) -> d_out
    {
        dim3 grid(C_ / 128, M_ / 128);
        gemm_tf32_kernel<1><<<grid, 256>>>(h_ao, w_proj, b_proj, out, C_, C_);
    }

    (void)out_size;
}

// round 9
// speedup vs baseline: 3.5549x; 3.1070x over previous
#include <cuda_runtime.h>
#include <cuda_fp16.h>
#include <cuda_bf16.h>
#include <cstddef>
#include <cstdint>
#include <math.h>

#define B_  2
#define N_  4096
#define C_  768
#define H_  8
#define DH  96
#define M_  (B_*N_)      // 8192
#define QKVN (3*C_)      // 2304

// Scratch (static __device__ globals)
__device__ float g_qkv[(size_t)M_*QKVN];   // [8192][2304] row-major
__device__ float g_ao[(size_t)M_*C_];      // [8192][768]

// HOST-side resolved DEVICE addresses (host-shadow/ATS bug fix from R7).
static float* h_qkv = nullptr;
static float* h_ao  = nullptr;

// ---------------------------------------------------------------------------
// tf32 helpers (GEMMs — unchanged from R8, proven)
// ---------------------------------------------------------------------------
__device__ __forceinline__ uint32_t f2tf32(float f) {
    uint32_t u;
    asm("cvt.rna.tf32.f32 %0, %1;" : "=r"(u) : "f"(f));
    return u;
}

__device__ __forceinline__ void mma_tf32(
    float& d0, float& d1, float& d2, float& d3,
    uint32_t a0, uint32_t a1, uint32_t a2, uint32_t a3,
    uint32_t b0, uint32_t b1)
{
    asm volatile(
        "mma.sync.aligned.m16n8k8.row.col.f32.tf32.tf32.f32 "
        "{%0,%1,%2,%3}, {%4,%5,%6,%7}, {%8,%9}, {%0,%1,%2,%3};\n"
        : "+f"(d0), "+f"(d1), "+f"(d2), "+f"(d3)
        : "r"(a0), "r"(a1), "r"(a2), "r"(a3), "r"(b0), "r"(b1));
}

template<int EPI>
__global__ void __launch_bounds__(256) gemm_tf32_kernel(
    const float* __restrict__ A, const float* __restrict__ Bm,
    const float* __restrict__ bias, float* __restrict__ Cout,
    int K, int Nw)
{
    __shared__ uint32_t As[2][128][12];
    __shared__ uint32_t Bs[2][8][132];

    const int t    = threadIdx.x;
    const int lane = t & 31;
    const int wid  = t >> 5;
    const int gid  = lane >> 2;
    const int tig  = lane & 3;
    const int warp_m = wid >> 2;
    const int warp_n = wid & 3;
    const int row0 = blockIdx.y * 128, col0 = blockIdx.x * 128;
    const int m_base = warp_m * 64, n_base = warp_n * 32;

    const int ar = t >> 1;
    const int ac = (t & 1) * 4;
    const int br = t >> 5;
    const int bn = (t & 31) * 4;

    float acc[4][4][4];
    #pragma unroll
    for (int mt = 0; mt < 4; mt++)
        #pragma unroll
        for (int nt = 0; nt < 4; nt++)
            #pragma unroll
            for (int r = 0; r < 4; r++) acc[mt][nt][r] = 0.f;

    const int KSTEPS = K / 8;
    {
        float4 fa = *(const float4*)(A + (size_t)(row0 + ar) * K + ac);
        float4 fb = *(const float4*)(Bm + (size_t)br * Nw + col0 + bn);
        *(uint4*)&As[0][ar][ac] = make_uint4(f2tf32(fa.x), f2tf32(fa.y), f2tf32(fa.z), f2tf32(fa.w));
        *(uint4*)&Bs[0][br][bn] = make_uint4(f2tf32(fb.x), f2tf32(fb.y), f2tf32(fb.z), f2tf32(fb.w));
    }
    __syncthreads();

    for (int kt = 0; kt < KSTEPS; kt++) {
        const int cur = kt & 1;
        float4 fa, fb;
        const bool more = (kt + 1 < KSTEPS);
        if (more) {
            int k0 = (kt + 1) * 8;
            fa = *(const float4*)(A + (size_t)(row0 + ar) * K + k0 + ac);
            fb = *(const float4*)(Bm + (size_t)(k0 + br) * Nw + col0 + bn);
        }
        uint32_t bf[4][2];
        #pragma unroll
        for (int nt = 0; nt < 4; nt++) {
            int n = n_base + nt * 8 + gid;
            bf[nt][0] = Bs[cur][tig][n];
            bf[nt][1] = Bs[cur][tig + 4][n];
        }
        #pragma unroll
        for (int mt = 0; mt < 4; mt++) {
            int mb = m_base + mt * 16;
            uint32_t a0 = As[cur][mb + gid][tig];
            uint32_t a1 = As[cur][mb + gid + 8][tig];
            uint32_t a2 = As[cur][mb + gid][tig + 4];
            uint32_t a3 = As[cur][mb + gid + 8][tig + 4];
            #pragma unroll
            for (int nt = 0; nt < 4; nt++)
                mma_tf32(acc[mt][nt][0], acc[mt][nt][1], acc[mt][nt][2], acc[mt][nt][3],
                         a0, a1, a2, a3, bf[nt][0], bf[nt][1]);
        }
        if (more) {
            *(uint4*)&As[cur ^ 1][ar][ac] = make_uint4(f2tf32(fa.x), f2tf32(fa.y), f2tf32(fa.z), f2tf32(fa.w));
            *(uint4*)&Bs[cur ^ 1][br][bn] = make_uint4(f2tf32(fb.x), f2tf32(fb.y), f2tf32(fb.z), f2tf32(fb.w));
        }
        __syncthreads();
    }

    #pragma unroll
    for (int mt = 0; mt < 4; mt++) {
        #pragma unroll
        for (int nt = 0; nt < 4; nt++) {
            int r0 = row0 + m_base + mt * 16 + gid;
            int c0 = col0 + n_base + nt * 8 + 2 * tig;
            float2 v01, v23;
            if (EPI == 1) {
                float bx = bias[c0], by = bias[c0 + 1];
                v01 = make_float2(acc[mt][nt][0] + bx, acc[mt][nt][1] + by);
                v23 = make_float2(acc[mt][nt][2] + bx, acc[mt][nt][3] + by);
            } else {
                v01 = make_float2(acc[mt][nt][0], acc[mt][nt][1]);
                v23 = make_float2(acc[mt][nt][2], acc[mt][nt][3]);
            }
            *(float2*)&Cout[(size_t)r0 * Nw + c0]       = v01;
            *(float2*)&Cout[(size_t)(r0 + 8) * Nw + c0] = v23;
        }
    }
}

// ---------------------------------------------------------------------------
// Tensor-core flash attention.
// Q-tile 128, KV-tile 64, 8 warps (warp w owns q rows w*16..w*16+15).
// S = (scale*Q)K^T via 3x bf16 split mma (hi/lo), fp32 accum  -> ~4e-6 error.
// P,V in fp16, PV via fp16 mma, fp32 accum                    -> ~4.9e-4.
// Softmax stats in registers (2 rows/thread, shfl.bfly over quad).
// Double-buffered K/V with register-staged prefetch. 1 CTA/SM.
// ---------------------------------------------------------------------------
#define QT 128
#define KT 64
#define QP 52    // b32 pitch for Qh/Ql/Kh/Kl rows (96 bf16 = 48 b32 + pad)
#define VP 36    // b32 pitch for Vt rows (64 fp16 = 32 b32 + pad) / Ps rows

#define OFF_QH  0
#define OFF_QL  (OFF_QH + QT*QP)       // 6656
#define OFF_KH0 (OFF_QL + QT*QP)       // 13312
#define OFF_KH1 (OFF_KH0 + KT*QP)      // 16640
#define OFF_KL0 (OFF_KH1 + KT*QP)      // 19968
#define OFF_KL1 (OFF_KL0 + KT*QP)      // 23296
#define OFF_VT0 (OFF_KL1 + KT*QP)      // 26624
#define OFF_VT1 (OFF_VT0 + DH*VP)      // 30080
#define OFF_PS  (OFF_VT1 + DH*VP)      // 33536
#define FLASH_SMEM_B32 (OFF_PS + QT*VP)     // 38144
#define FLASH_SMEM (FLASH_SMEM_B32 * 4)     // 152576 bytes

__device__ __forceinline__ void mma_bf16x(float* d, const uint32_t* a, uint32_t b0, uint32_t b1) {
    asm volatile(
        "mma.sync.aligned.m16n8k16.row.col.f32.bf16.bf16.f32 "
        "{%0,%1,%2,%3}, {%4,%5,%6,%7}, {%8,%9}, {%0,%1,%2,%3};\n"
        : "+f"(d[0]), "+f"(d[1]), "+f"(d[2]), "+f"(d[3])
        : "r"(a[0]), "r"(a[1]), "r"(a[2]), "r"(a[3]), "r"(b0), "r"(b1));
}
__device__ __forceinline__ void mma_f16x(float* d, const uint32_t* a, uint32_t b0, uint32_t b1) {
    asm volatile(
        "mma.sync.aligned.m16n8k16.row.col.f32.f16.f16.f32 "
        "{%0,%1,%2,%3}, {%4,%5,%6,%7}, {%8,%9}, {%0,%1,%2,%3};\n"
        : "+f"(d[0]), "+f"(d[1]), "+f"(d[2]), "+f"(d[3])
        : "r"(a[0]), "r"(a[1]), "r"(a[2]), "r"(a[3]), "r"(b0), "r"(b1));
}

__device__ __forceinline__ uint16_t bf_bits(__nv_bfloat16 h) {
    return *reinterpret_cast<uint16_t*>(&h);
}
// Split f into bf16 hi + lo (residual), return bits.
__device__ __forceinline__ void split_bf(float x, uint16_t& hb, uint16_t& lb) {
    __nv_bfloat16 h = __float2bfloat16(x);           // RN
    float r = x - __bfloat162float(h);
    __nv_bfloat16 l = __float2bfloat16(r);
    hb = bf_bits(h); lb = bf_bits(l);
}
__device__ __forceinline__ uint32_t pack16(uint16_t lo, uint16_t hi) {
    return (uint32_t)lo | ((uint32_t)hi << 16);
}
__device__ __forceinline__ uint32_t pack_h2(float a, float b) {
    __half2 h = __floats2half2_rn(a, b);
    return *reinterpret_cast<uint32_t*>(&h);
}

__global__ void __launch_bounds__(256) flash_tc_kernel()
{
    extern __shared__ uint32_t su[];
    const int t    = threadIdx.x;
    const int lane = t & 31;
    const int w    = t >> 5;
    const int gid  = lane >> 2;
    const int tig  = lane & 3;
    const int bh = blockIdx.y;
    const int b  = bh >> 3;
    const int h  = bh & 7;
    const int q0 = blockIdx.x * QT;
    const float scale = 0.1020620726159657f;   // 96^-0.5

    const float* qb = g_qkv + (size_t)b * N_ * QKVN + h * DH;
    const float* kb = qb + C_;
    const float* vb = qb + 2 * C_;

    // ---- Prologue: Q (scaled) -> Qh/Ql;  K/V tile 0 -> buffers 0 ----
    #pragma unroll
    for (int i = 0; i < 12; i++) {
        int f = i * 256 + t;
        int row = f / 24, q = f - row * 24;
        float4 v = *(const float4*)(qb + (size_t)(q0 + row) * QKVN + q * 4);
        v.x *= scale; v.y *= scale; v.z *= scale; v.w *= scale;
        uint16_t h0,l0,h1,l1,h2,l2,h3,l3;
        split_bf(v.x,h0,l0); split_bf(v.y,h1,l1); split_bf(v.z,h2,l2); split_bf(v.w,h3,l3);
        su[OFF_QH + row*QP + q*2]     = pack16(h0,h1);
        su[OFF_QH + row*QP + q*2 + 1] = pack16(h2,h3);
        su[OFF_QL + row*QP + q*2]     = pack16(l0,l1);
        su[OFF_QL + row*QP + q*2 + 1] = pack16(l2,l3);
    }
    #pragma unroll
    for (int i = 0; i < 6; i++) {
        int f = i * 256 + t;
        int row = f / 24, q = f - row * 24;
        float4 kv = *(const float4*)(kb + (size_t)row * QKVN + q * 4);
        uint16_t h0,l0,h1,l1,h2,l2,h3,l3;
        split_bf(kv.x,h0,l0); split_bf(kv.y,h1,l1); split_bf(kv.z,h2,l2); split_bf(kv.w,h3,l3);
        su[OFF_KH0 + row*QP + q*2]     = pack16(h0,h1);
        su[OFF_KH0 + row*QP + q*2 + 1] = pack16(h2,h3);
        su[OFF_KL0 + row*QP + q*2]     = pack16(l0,l1);
        su[OFF_KL0 + row*QP + q*2 + 1] = pack16(l2,l3);
        float4 vv = *(const float4*)(vb + (size_t)row * QKVN + q * 4);
        __half* vt = (__half*)(su + OFF_VT0);
        vt[(q*4+0)*(VP*2) + row] = __float2half(vv.x);
        vt[(q*4+1)*(VP*2) + row] = __float2half(vv.y);
        vt[(q*4+2)*(VP*2) + row] = __float2half(vv.z);
        vt[(q*4+3)*(VP*2) + row] = __float2half(vv.w);
    }
    __syncthreads();

    float m0 = -INFINITY, m1 = -INFINITY, l0r = 0.f, l1r = 0.f;
    float o[12][4];
    #pragma unroll
    for (int nt = 0; nt < 12; nt++)
        #pragma unroll
        for (int r = 0; r < 4; r++) o[nt][r] = 0.f;

    const int NTILES = N_ / KT;   // 64
    for (int it = 0; it < NTILES; it++) {
        const int cur = it & 1;
        const bool more = (it + 1 < NTILES);

        // Register-stage next K/V tile (loads overlap the mmas below)
        float4 kst[6], vst[6];
        if (more) {
            int k0n = (it + 1) * KT;
            #pragma unroll
            for (int i = 0; i < 6; i++) {
                int f = i * 256 + t;
                int row = f / 24, q = f - row * 24;
                kst[i] = *(const float4*)(kb + (size_t)(k0n + row) * QKVN + q * 4);
                vst[i] = *(const float4*)(vb + (size_t)(k0n + row) * QKVN + q * 4);
            }
        }

        const uint32_t* KH = su + (cur ? OFF_KH1 : OFF_KH0);
        const uint32_t* KL = su + (cur ? OFF_KL1 : OFF_KL0);
        const uint32_t* VT = su + (cur ? OFF_VT1 : OFF_VT0);

        // ---- S = Qs * K^T (3x bf16 split mma), fp32 accum ----
        float s[8][4];
        #pragma unroll
        for (int nt = 0; nt < 8; nt++)
            #pragma unroll
            for (int r = 0; r < 4; r++) s[nt][r] = 0.f;

        #pragma unroll
        for (int j = 0; j < 6; j++) {
            const int qi = (w*16 + gid)*QP + j*8 + tig;
            uint32_t ah[4], al[4];
            ah[0] = su[OFF_QH + qi];            ah[1] = su[OFF_QH + qi + 8*QP];
            ah[2] = su[OFF_QH + qi + 4];        ah[3] = su[OFF_QH + qi + 8*QP + 4];
            al[0] = su[OFF_QL + qi];            al[1] = su[OFF_QL + qi + 8*QP];
            al[2] = su[OFF_QL + qi + 4];        al[3] = su[OFF_QL + qi + 8*QP + 4];
            #pragma unroll
            for (int nt = 0; nt < 8; nt++) {
                const int ki = (nt*8 + gid)*QP + j*8 + tig;
                uint32_t bh0 = KH[ki], bh1 = KH[ki + 4];
                uint32_t bl0 = KL[ki], bl1 = KL[ki + 4];
                mma_bf16x(s[nt], ah, bh0, bh1);
                mma_bf16x(s[nt], ah, bl0, bl1);
                mma_bf16x(s[nt], al, bh0, bh1);
            }
        }

        // ---- Softmax (rows gid, gid+8 of this warp's 16) ----
        float mr0 = -INFINITY, mr1 = -INFINITY;
        #pragma unroll
        for (int nt = 0; nt < 8; nt++) {
            mr0 = fmaxf(mr0, fmaxf(s[nt][0], s[nt][1]));
            mr1 = fmaxf(mr1, fmaxf(s[nt][2], s[nt][3]));
        }
        mr0 = fmaxf(mr0, __shfl_xor_sync(0xffffffffu, mr0, 1));
        mr0 = fmaxf(mr0, __shfl_xor_sync(0xffffffffu, mr0, 2));
        mr1 = fmaxf(mr1, __shfl_xor_sync(0xffffffffu, mr1, 1));
        mr1 = fmaxf(mr1, __shfl_xor_sync(0xffffffffu, mr1, 2));
        const float mn0 = fmaxf(m0, mr0), mn1 = fmaxf(m1, mr1);
        const float sc0 = __expf(m0 - mn0), sc1 = __expf(m1 - mn1);

        float rs0 = 0.f, rs1 = 0.f;
        #pragma unroll
        for (int nt = 0; nt < 8; nt++) {
            float p00 = __expf(s[nt][0] - mn0);
            float p01 = __expf(s[nt][1] - mn0);
            float p10 = __expf(s[nt][2] - mn1);
            float p11 = __expf(s[nt][3] - mn1);
            rs0 += p00 + p01;
            rs1 += p10 + p11;
            su[OFF_PS + (w*16 + gid)*VP + nt*4 + tig]     = pack_h2(p00, p01);
            su[OFF_PS + (w*16 + gid + 8)*VP + nt*4 + tig] = pack_h2(p10, p11);
        }
        rs0 += __shfl_xor_sync(0xffffffffu, rs0, 1);
        rs0 += __shfl_xor_sync(0xffffffffu, rs0, 2);
        rs1 += __shfl_xor_sync(0xffffffffu, rs1, 1);
        rs1 += __shfl_xor_sync(0xffffffffu, rs1, 2);

        l0r = l0r * sc0 + rs0;
        l1r = l1r * sc1 + rs1;
        m0 = mn0; m1 = mn1;

        #pragma unroll
        for (int nt = 0; nt < 12; nt++) {
            o[nt][0] *= sc0; o[nt][1] *= sc0;
            o[nt][2] *= sc1; o[nt][3] *= sc1;
        }
        __syncwarp();

        // ---- O += P @ V (fp16 mma, fp32 accum) ----
        #pragma unroll
        for (int jk = 0; jk < 4; jk++) {
            const int pi = (w*16 + gid)*VP + jk*8 + tig;
            uint32_t pa[4];
            pa[0] = su[OFF_PS + pi];        pa[1] = su[OFF_PS + pi + 8*VP];
            pa[2] = su[OFF_PS + pi + 4];    pa[3] = su[OFF_PS + pi + 8*VP + 4];
            #pragma unroll
            for (int nt = 0; nt < 12; nt++) {
                const int vi = (nt*8 + gid)*VP + jk*8 + tig;
                mma_f16x(o[nt], pa, VT[vi], VT[vi + 4]);
            }
        }

        // ---- Store staged K/V into the other buffer ----
        if (more) {
            uint32_t* KHn = su + (cur ? OFF_KH0 : OFF_KH1);
            uint32_t* KLn = su + (cur ? OFF_KL0 : OFF_KL1);
            __half* vtn = (__half*)(su + (cur ? OFF_VT0 : OFF_VT1));
            #pragma unroll
            for (int i = 0; i < 6; i++) {
                int f = i * 256 + t;
                int row = f / 24, q = f - row * 24;
                uint16_t h0,l0,h1,l1,h2,l2,h3,l3;
                split_bf(kst[i].x,h0,l0); split_bf(kst[i].y,h1,l1);
                split_bf(kst[i].z,h2,l2); split_bf(kst[i].w,h3,l3);
                KHn[row*QP + q*2]     = pack16(h0,h1);
                KHn[row*QP + q*2 + 1] = pack16(h2,h3);
                KLn[row*QP + q*2]     = pack16(l0,l1);
                KLn[row*QP + q*2 + 1] = pack16(l2,l3);
                vtn[(q*4+0)*(VP*2) + row] = __float2half(vst[i].x);
                vtn[(q*4+1)*(VP*2) + row] = __float2half(vst[i].y);
                vtn[(q*4+2)*(VP*2) + row] = __float2half(vst[i].z);
                vtn[(q*4+3)*(VP*2) + row] = __float2half(vst[i].w);
            }
        }
        __syncthreads();
    }

    // ---- Epilogue ----
    const float inv0 = 1.f / l0r, inv1 = 1.f / l1r;
    const size_t orow0 = ((size_t)b * N_ + q0 + w*16 + gid) * C_ + h * DH;
    const size_t orow1 = orow0 + (size_t)8 * C_;
    #pragma unroll
    for (int nt = 0; nt < 12; nt++) {
        *(float2*)(g_ao + orow0 + nt*8 + 2*tig) = make_float2(o[nt][0]*inv0, o[nt][1]*inv0);
        *(float2*)(g_ao + orow1 + nt*8 + 2*tig) = make_float2(o[nt][2]*inv1, o[nt][3]*inv1);
    }
}

// ---------------------------------------------------------------------------
// Static initializer: device addrs, smem attribute, warmups, graph rehearsal.
// ---------------------------------------------------------------------------
namespace {
struct ModulePreloader {
    ModulePreloader() {
        if (cudaFree(0) != cudaSuccess) return;
        void* p = nullptr;
        if (cudaGetSymbolAddress(&p, g_qkv) != cudaSuccess) return;
        h_qkv = (float*)p;
        if (cudaGetSymbolAddress(&p, g_ao) != cudaSuccess) return;
        h_ao = (float*)p;

        cudaFuncSetAttribute(flash_tc_kernel,
                             cudaFuncAttributeMaxDynamicSharedMemorySize,
                             FLASH_SMEM);

        dim3 g0(QKVN / 128, M_ / 128);
        dim3 g1(N_ / QT, B_ * H_);
        dim3 g2(C_ / 128, M_ / 128);

        gemm_tf32_kernel<0><<<g0, 256>>>(h_ao, h_ao, nullptr, h_qkv, C_, QKVN);
        flash_tc_kernel<<<g1, 256, FLASH_SMEM>>>();
        gemm_tf32_kernel<1><<<g2, 256>>>(h_ao, h_ao, h_ao, h_qkv, C_, C_);
        if (cudaDeviceSynchronize() != cudaSuccess) return;

        cudaStream_t s = nullptr;
        if (cudaStreamCreate(&s) != cudaSuccess) return;
        cudaGraph_t graph = nullptr;
        cudaGraphExec_t exec = nullptr;
        if (cudaStreamBeginCapture(s, cudaStreamCaptureModeRelaxed) == cudaSuccess) {
            gemm_tf32_kernel<0><<<g0, 256, 0, s>>>(h_ao, h_ao, nullptr, h_qkv, C_, QKVN);
            flash_tc_kernel<<<g1, 256, FLASH_SMEM, s>>>();
            gemm_tf32_kernel<1><<<g2, 256, 0, s>>>(h_ao, h_ao, h_ao, h_qkv, C_, C_);
            if (cudaStreamEndCapture(s, &graph) == cudaSuccess && graph) {
                if (cudaGraphInstantiate(&exec, graph, nullptr, nullptr, 0) == cudaSuccess && exec) {
                    cudaGraphLaunch(exec, s);
                    cudaStreamSynchronize(s);
                    cudaGraphExecDestroy(exec);
                }
                cudaGraphDestroy(graph);
            }
        }
        cudaStreamDestroy(s);
        cudaDeviceSynchronize();
    }
};
ModulePreloader preloader_;
}

// ---------------------------------------------------------------------------
extern "C" void kernel_launch(void* const* d_in, const int* in_sizes, int n_in,
                              void* d_out, int out_size)
{
    const float* x      = nullptr;   // 6291456
    const float* w_qkv  = nullptr;   // 1769472
    const float* w_proj = nullptr;   // 589824
    const float* b_proj = nullptr;   // 768
    for (int i = 0; i < n_in; i++) {
        switch (in_sizes[i]) {
            case 6291456: x      = (const float*)d_in[i]; break;
            case 1769472: w_qkv  = (const float*)d_in[i]; break;
            case 589824:  w_proj = (const float*)d_in[i]; break;
            case 768:     b_proj = (const float*)d_in[i]; break;
            default: break;
        }
    }
    if (!x)      x      = (const float*)d_in[0];
    if (!w_qkv)  w_qkv  = (const float*)d_in[1];
    if (!w_proj) w_proj = (const float*)d_in[2];
    if (!b_proj) b_proj = (const float*)d_in[3];

    float* out = (float*)d_out;

    if (!h_qkv) { void* p; cudaGetSymbolAddress(&p, g_qkv); h_qkv = (float*)p; }
    if (!h_ao)  { void* p; cudaGetSymbolAddress(&p, g_ao);  h_ao  = (float*)p; }

    // 1) QKV GEMM (tf32) -> g_qkv
    {
        dim3 grid(QKVN / 128, M_ / 128);
        gemm_tf32_kernel<0><<<grid, 256>>>(x, w_qkv, nullptr, h_qkv, C_, QKVN);
    }
    // 2) Tensor-core flash attention -> g_ao
    {
        dim3 grid(N_ / QT, B_ * H_);
        flash_tc_kernel<<<grid, 256, FLASH_SMEM>>>();
    }
    // 3) Projection GEMM + bias (tf32) -> d_out
    {
        dim3 grid(C_ / 128, M_ / 128);
        gemm_tf32_kernel<1><<<grid, 256>>>(h_ao, w_proj, b_proj, out, C_, C_);
    }
    (void)out_size;
}

// round 10
// speedup vs baseline: 4.6993x; 1.3219x over previous
#include <cuda_runtime.h>
#include <cuda_fp16.h>
#include <cuda_bf16.h>
#include <cstddef>
#include <cstdint>
#include <math.h>

#define B_  2
#define N_  4096
#define C_  768
#define H_  8
#define DH  96
#define M_  (B_*N_)      // 8192
#define QKVN (3*C_)      // 2304
#define QSCALE 0.1020620726159657f   // 96^-0.5

// Scratch (static __device__ globals)
__device__ __half g_qh[(size_t)M_*C_];        // scale*Q, fp16 [m][768]
__device__ __half g_kh[(size_t)M_*C_];        // K hi fp16 [m][768]
__device__ __half g_kl[(size_t)M_*C_];        // K lo fp16 [m][768]
__device__ __half g_vt[(size_t)B_*H_*DH*N_];  // V^T fp16 [bh][d][n]
__device__ float  g_ao[(size_t)M_*C_];        // attention out fp32 [m][768]

// HOST-side resolved DEVICE address (host-shadow/ATS bug fix from R7).
static float* h_ao = nullptr;

// ---------------------------------------------------------------------------
// tf32 helpers
// ---------------------------------------------------------------------------
__device__ __forceinline__ uint32_t f2tf32(float f) {
    uint32_t u;
    asm("cvt.rna.tf32.f32 %0, %1;" : "=r"(u) : "f"(f));
    return u;
}

__device__ __forceinline__ void mma_tf32(
    float& d0, float& d1, float& d2, float& d3,
    uint32_t a0, uint32_t a1, uint32_t a2, uint32_t a3,
    uint32_t b0, uint32_t b1)
{
    asm volatile(
        "mma.sync.aligned.m16n8k8.row.col.f32.tf32.tf32.f32 "
        "{%0,%1,%2,%3}, {%4,%5,%6,%7}, {%8,%9}, {%0,%1,%2,%3};\n"
        : "+f"(d0), "+f"(d1), "+f"(d2), "+f"(d3)
        : "r"(a0), "r"(a1), "r"(a2), "r"(a3), "r"(b0), "r"(b1));
}

// ---------------------------------------------------------------------------
// tf32 GEMM. EPI=0 (QKV): epilogue converts per region and writes fp16
// scratch (g_qh scaled / g_kh+g_kl split / g_vt transposed). No fp32 C.
// EPI=1 (proj): +bias, fp32 C.
// CTA tile 128x128 — for EPI=0 each CTA column block lies wholly in one of
// Q/K/V (boundaries 768/1536 are multiples of 128), so the branch is uniform.
// ---------------------------------------------------------------------------
template<int EPI>
__global__ void __launch_bounds__(256) gemm_tf32_kernel(
    const float* __restrict__ A, const float* __restrict__ Bm,
    const float* __restrict__ bias, float* __restrict__ Cout,
    int K, int Nw)
{
    __shared__ uint32_t As[2][128][12];
    __shared__ uint32_t Bs[2][8][132];

    const int t    = threadIdx.x;
    const int lane = t & 31;
    const int wid  = t >> 5;
    const int gid  = lane >> 2;
    const int tig  = lane & 3;
    const int warp_m = wid >> 2;
    const int warp_n = wid & 3;
    const int row0 = blockIdx.y * 128, col0 = blockIdx.x * 128;
    const int m_base = warp_m * 64, n_base = warp_n * 32;

    const int ar = t >> 1;
    const int ac = (t & 1) * 4;
    const int br = t >> 5;
    const int bn = (t & 31) * 4;

    float acc[4][4][4];
    #pragma unroll
    for (int mt = 0; mt < 4; mt++)
        #pragma unroll
        for (int nt = 0; nt < 4; nt++)
            #pragma unroll
            for (int r = 0; r < 4; r++) acc[mt][nt][r] = 0.f;

    const int KSTEPS = K / 8;
    {
        float4 fa = *(const float4*)(A + (size_t)(row0 + ar) * K + ac);
        float4 fb = *(const float4*)(Bm + (size_t)br * Nw + col0 + bn);
        *(uint4*)&As[0][ar][ac] = make_uint4(f2tf32(fa.x), f2tf32(fa.y), f2tf32(fa.z), f2tf32(fa.w));
        *(uint4*)&Bs[0][br][bn] = make_uint4(f2tf32(fb.x), f2tf32(fb.y), f2tf32(fb.z), f2tf32(fb.w));
    }
    __syncthreads();

    for (int kt = 0; kt < KSTEPS; kt++) {
        const int cur = kt & 1;
        float4 fa, fb;
        const bool more = (kt + 1 < KSTEPS);
        if (more) {
            int k0 = (kt + 1) * 8;
            fa = *(const float4*)(A + (size_t)(row0 + ar) * K + k0 + ac);
            fb = *(const float4*)(Bm + (size_t)(k0 + br) * Nw + col0 + bn);
        }
        uint32_t bf[4][2];
        #pragma unroll
        for (int nt = 0; nt < 4; nt++) {
            int n = n_base + nt * 8 + gid;
            bf[nt][0] = Bs[cur][tig][n];
            bf[nt][1] = Bs[cur][tig + 4][n];
        }
        #pragma unroll
        for (int mt = 0; mt < 4; mt++) {
            int mb = m_base + mt * 16;
            uint32_t a0 = As[cur][mb + gid][tig];
            uint32_t a1 = As[cur][mb + gid + 8][tig];
            uint32_t a2 = As[cur][mb + gid][tig + 4];
            uint32_t a3 = As[cur][mb + gid + 8][tig + 4];
            #pragma unroll
            for (int nt = 0; nt < 4; nt++)
                mma_tf32(acc[mt][nt][0], acc[mt][nt][1], acc[mt][nt][2], acc[mt][nt][3],
                         a0, a1, a2, a3, bf[nt][0], bf[nt][1]);
        }
        if (more) {
            *(uint4*)&As[cur ^ 1][ar][ac] = make_uint4(f2tf32(fa.x), f2tf32(fa.y), f2tf32(fa.z), f2tf32(fa.w));
            *(uint4*)&Bs[cur ^ 1][br][bn] = make_uint4(f2tf32(fb.x), f2tf32(fb.y), f2tf32(fb.z), f2tf32(fb.w));
        }
        __syncthreads();
    }

    #pragma unroll
    for (int mt = 0; mt < 4; mt++) {
        #pragma unroll
        for (int nt = 0; nt < 4; nt++) {
            int r0 = row0 + m_base + mt * 16 + gid;
            int c0 = col0 + n_base + nt * 8 + 2 * tig;
            if (EPI == 1) {
                float bx = bias[c0], by = bias[c0 + 1];
                *(float2*)&Cout[(size_t)r0 * Nw + c0] =
                    make_float2(acc[mt][nt][0] + bx, acc[mt][nt][1] + by);
                *(float2*)&Cout[(size_t)(r0 + 8) * Nw + c0] =
                    make_float2(acc[mt][nt][2] + bx, acc[mt][nt][3] + by);
            } else {
                #pragma unroll
                for (int half_ : {0, 1}) {
                    int m = r0 + half_ * 8;
                    float x = acc[mt][nt][half_ * 2 + 0];
                    float y = acc[mt][nt][half_ * 2 + 1];
                    if (col0 < C_) {                       // Q: scale + fp16
                        *(__half2*)&g_qh[(size_t)m * C_ + c0] =
                            __floats2half2_rn(x * QSCALE, y * QSCALE);
                    } else if (col0 < 2 * C_) {            // K: hi/lo split
                        int ch = c0 - C_;
                        __half hx = __float2half_rn(x), hy = __float2half_rn(y);
                        float rx = x - __half2float(hx), ry = y - __half2float(hy);
                        *(__half2*)&g_kh[(size_t)m * C_ + ch] = __halves2half2(hx, hy);
                        *(__half2*)&g_kl[(size_t)m * C_ + ch] =
                            __halves2half2(__float2half_rn(rx), __float2half_rn(ry));
                    } else {                               // V: fp16, transposed
                        int cv = c0 - 2 * C_;
                        int hh = cv / DH, d = cv - hh * DH;
                        int bb = m >> 12, n = m & (N_ - 1);
                        size_t vbase = ((size_t)(bb * H_ + hh)) * DH;
                        g_vt[(vbase + d) * N_ + n]     = __float2half_rn(x);
                        g_vt[(vbase + d + 1) * N_ + n] = __float2half_rn(y);
                    }
                }
            }
        }
    }
}

// ---------------------------------------------------------------------------
// Tensor-core flash attention, zero-conversion loaders.
// Q-tile 128, KV-tile 64, 8 warps (warp w owns q rows w*16..w*16+15).
// S = qh·kh + qh·kl (2x fp16 mma, fp32 accum): err ~2^-12 on scaled S.
// PV fp16 mma. Softmax stats in registers (2 rows/thread, shfl over quad).
// Double-buffered K/V with register-staged uint4 prefetch.
// ---------------------------------------------------------------------------
#define QT 128
#define KT 64
#define QP 52    // b32 pitch for QH/KH/KL rows (96 fp16 = 48 b32 + pad)
#define VP 36    // b32 pitch for VT rows (64 fp16 = 32 b32 + pad) / PS rows

#define OFF_QH  0
#define OFF_KH0 (OFF_QH + QT*QP)       // 6656
#define OFF_KH1 (OFF_KH0 + KT*QP)      // 9984
#define OFF_KL0 (OFF_KH1 + KT*QP)      // 13312
#define OFF_KL1 (OFF_KL0 + KT*QP)      // 16640
#define OFF_VT0 (OFF_KL1 + KT*QP)      // 19968
#define OFF_VT1 (OFF_VT0 + DH*VP)      // 23424
#define OFF_PS  (OFF_VT1 + DH*VP)      // 26880
#define FLASH_SMEM_B32 (OFF_PS + QT*VP)     // 31488
#define FLASH_SMEM (FLASH_SMEM_B32 * 4)     // 125952 bytes

__device__ __forceinline__ void mma_f16x(float* d, const uint32_t* a, uint32_t b0, uint32_t b1) {
    asm volatile(
        "mma.sync.aligned.m16n8k16.row.col.f32.f16.f16.f32 "
        "{%0,%1,%2,%3}, {%4,%5,%6,%7}, {%8,%9}, {%0,%1,%2,%3};\n"
        : "+f"(d[0]), "+f"(d[1]), "+f"(d[2]), "+f"(d[3])
        : "r"(a[0]), "r"(a[1]), "r"(a[2]), "r"(a[3]), "r"(b0), "r"(b1));
}
__device__ __forceinline__ uint32_t pack_h2(float a, float b) {
    __half2 h = __floats2half2_rn(a, b);
    return *reinterpret_cast<uint32_t*>(&h);
}

__global__ void __launch_bounds__(256) flash_tc_kernel()
{
    extern __shared__ uint32_t su[];
    const int t    = threadIdx.x;
    const int lane = t & 31;
    const int w    = t >> 5;
    const int gid  = lane >> 2;
    const int tig  = lane & 3;
    const int bh = blockIdx.y;
    const int b  = bh >> 3;
    const int h  = bh & 7;
    const int q0 = blockIdx.x * QT;

    const __half* qg = g_qh + ((size_t)b * N_) * C_ + h * DH;   // +n*C_+d
    const __half* kg = g_kh + ((size_t)b * N_) * C_ + h * DH;
    const __half* lg = g_kl + ((size_t)b * N_) * C_ + h * DH;
    const __half* vg = g_vt + ((size_t)bh * DH) * N_;           // +d*N_+n

    // ---- Prologue: Q tile + K/V tile 0 (pure uint4 copies) ----
    #pragma unroll
    for (int i = 0; i < 6; i++) {                  // Q: 128 rows x 12 uint4
        int f = i * 256 + t;
        int row = f / 12, qq = f - row * 12;
        uint4 v = *(const uint4*)(qg + (size_t)(q0 + row) * C_ + qq * 8);
        *(uint4*)&su[OFF_QH + row * QP + qq * 4] = v;
    }
    #pragma unroll
    for (int i = 0; i < 3; i++) {                  // K hi/lo: 64 rows x 12 uint4
        int f = i * 256 + t;
        int row = f / 12, qq = f - row * 12;
        *(uint4*)&su[OFF_KH0 + row * QP + qq * 4] =
            *(const uint4*)(kg + (size_t)row * C_ + qq * 8);
        *(uint4*)&su[OFF_KL0 + row * QP + qq * 4] =
            *(const uint4*)(lg + (size_t)row * C_ + qq * 8);
    }
    #pragma unroll
    for (int i = 0; i < 3; i++) {                  // V^T: 96 rows x 8 uint4
        int f = i * 256 + t;
        int d = f / 8, nn = f - d * 8;
        *(uint4*)&su[OFF_VT0 + d * VP + nn * 4] =
            *(const uint4*)(vg + (size_t)d * N_ + nn * 8);
    }
    __syncthreads();

    float m0 = -INFINITY, m1 = -INFINITY, l0r = 0.f, l1r = 0.f;
    float o[12][4];
    #pragma unroll
    for (int nt = 0; nt < 12; nt++)
        #pragma unroll
        for (int r = 0; r < 4; r++) o[nt][r] = 0.f;

    const int NTILES = N_ / KT;   // 64
    for (int it = 0; it < NTILES; it++) {
        const int cur = it & 1;
        const bool more = (it + 1 < NTILES);

        // Register-stage next K/V tile (LDGs overlap the mmas below)
        uint4 kst[3], lst[3], vst[3];
        if (more) {
            int k0n = (it + 1) * KT;
            #pragma unroll
            for (int i = 0; i < 3; i++) {
                int f = i * 256 + t;
                int row = f / 12, qq = f - row * 12;
                kst[i] = *(const uint4*)(kg + (size_t)(k0n + row) * C_ + qq * 8);
                lst[i] = *(const uint4*)(lg + (size_t)(k0n + row) * C_ + qq * 8);
            }
            #pragma unroll
            for (int i = 0; i < 3; i++) {
                int f = i * 256 + t;
                int d = f / 8, nn = f - d * 8;
                vst[i] = *(const uint4*)(vg + (size_t)d * N_ + k0n + nn * 8);
            }
        }

        const uint32_t* KH = su + (cur ? OFF_KH1 : OFF_KH0);
        const uint32_t* KL = su + (cur ? OFF_KL1 : OFF_KL0);
        const uint32_t* VT = su + (cur ? OFF_VT1 : OFF_VT0);

        // ---- S = Qs*K^T: 2x fp16 mma per (j,nt), fp32 accum ----
        float s[8][4];
        #pragma unroll
        for (int nt = 0; nt < 8; nt++)
            #pragma unroll
            for (int r = 0; r < 4; r++) s[nt][r] = 0.f;

        #pragma unroll
        for (int j = 0; j < 6; j++) {
            const int qi = (w*16 + gid)*QP + j*8 + tig;
            uint32_t ah[4];
            ah[0] = su[OFF_QH + qi];       ah[1] = su[OFF_QH + qi + 8*QP];
            ah[2] = su[OFF_QH + qi + 4];   ah[3] = su[OFF_QH + qi + 8*QP + 4];
            #pragma unroll
            for (int nt = 0; nt < 8; nt++) {
                const int ki = (nt*8 + gid)*QP + j*8 + tig;
                mma_f16x(s[nt], ah, KH[ki], KH[ki + 4]);
                mma_f16x(s[nt], ah, KL[ki], KL[ki + 4]);
            }
        }

        // ---- Softmax (rows gid, gid+8 of this warp's 16) ----
        float mr0 = -INFINITY, mr1 = -INFINITY;
        #pragma unroll
        for (int nt = 0; nt < 8; nt++) {
            mr0 = fmaxf(mr0, fmaxf(s[nt][0], s[nt][1]));
            mr1 = fmaxf(mr1, fmaxf(s[nt][2], s[nt][3]));
        }
        mr0 = fmaxf(mr0, __shfl_xor_sync(0xffffffffu, mr0, 1));
        mr0 = fmaxf(mr0, __shfl_xor_sync(0xffffffffu, mr0, 2));
        mr1 = fmaxf(mr1, __shfl_xor_sync(0xffffffffu, mr1, 1));
        mr1 = fmaxf(mr1, __shfl_xor_sync(0xffffffffu, mr1, 2));
        const float mn0 = fmaxf(m0, mr0), mn1 = fmaxf(m1, mr1);
        const float sc0 = __expf(m0 - mn0), sc1 = __expf(m1 - mn1);

        float rs0 = 0.f, rs1 = 0.f;
        #pragma unroll
        for (int nt = 0; nt < 8; nt++) {
            float p00 = __expf(s[nt][0] - mn0);
            float p01 = __expf(s[nt][1] - mn0);
            float p10 = __expf(s[nt][2] - mn1);
            float p11 = __expf(s[nt][3] - mn1);
            rs0 += p00 + p01;
            rs1 += p10 + p11;
            su[OFF_PS + (w*16 + gid)*VP + nt*4 + tig]     = pack_h2(p00, p01);
            su[OFF_PS + (w*16 + gid + 8)*VP + nt*4 + tig] = pack_h2(p10, p11);
        }
        rs0 += __shfl_xor_sync(0xffffffffu, rs0, 1);
        rs0 += __shfl_xor_sync(0xffffffffu, rs0, 2);
        rs1 += __shfl_xor_sync(0xffffffffu, rs1, 1);
        rs1 += __shfl_xor_sync(0xffffffffu, rs1, 2);

        l0r = l0r * sc0 + rs0;
        l1r = l1r * sc1 + rs1;
        m0 = mn0; m1 = mn1;

        #pragma unroll
        for (int nt = 0; nt < 12; nt++) {
            o[nt][0] *= sc0; o[nt][1] *= sc0;
            o[nt][2] *= sc1; o[nt][3] *= sc1;
        }
        __syncwarp();

        // ---- O += P @ V (fp16 mma) ----
        #pragma unroll
        for (int jk = 0; jk < 4; jk++) {
            const int pi = (w*16 + gid)*VP + jk*8 + tig;
            uint32_t pa[4];
            pa[0] = su[OFF_PS + pi];       pa[1] = su[OFF_PS + pi + 8*VP];
            pa[2] = su[OFF_PS + pi + 4];   pa[3] = su[OFF_PS + pi + 8*VP + 4];
            #pragma unroll
            for (int nt = 0; nt < 12; nt++) {
                const int vi = (nt*8 + gid)*VP + jk*8 + tig;
                mma_f16x(o[nt], pa, VT[vi], VT[vi + 4]);
            }
        }

        // ---- Store staged K/V into the other buffer ----
        if (more) {
            uint32_t* KHn = su + (cur ? OFF_KH0 : OFF_KH1);
            uint32_t* KLn = su + (cur ? OFF_KL0 : OFF_KL1);
            uint32_t* VTn = su + (cur ? OFF_VT0 : OFF_VT1);
            #pragma unroll
            for (int i = 0; i < 3; i++) {
                int f = i * 256 + t;
                int row = f / 12, qq = f - row * 12;
                *(uint4*)&KHn[row * QP + qq * 4] = kst[i];
                *(uint4*)&KLn[row * QP + qq * 4] = lst[i];
            }
            #pragma unroll
            for (int i = 0; i < 3; i++) {
                int f = i * 256 + t;
                int d = f / 8, nn = f - d * 8;
                *(uint4*)&VTn[d * VP + nn * 4] = vst[i];
            }
        }
        __syncthreads();
    }

    // ---- Epilogue ----
    const float inv0 = 1.f / l0r, inv1 = 1.f / l1r;
    const size_t orow0 = ((size_t)b * N_ + q0 + w*16 + gid) * C_ + h * DH;
    const size_t orow1 = orow0 + (size_t)8 * C_;
    #pragma unroll
    for (int nt = 0; nt < 12; nt++) {
        *(float2*)(g_ao + orow0 + nt*8 + 2*tig) = make_float2(o[nt][0]*inv0, o[nt][1]*inv0);
        *(float2*)(g_ao + orow1 + nt*8 + 2*tig) = make_float2(o[nt][2]*inv1, o[nt][3]*inv1);
    }
}

// ---------------------------------------------------------------------------
// Static initializer: device addrs, smem attribute, warmups, graph rehearsal.
// ---------------------------------------------------------------------------
namespace {
struct ModulePreloader {
    ModulePreloader() {
        if (cudaFree(0) != cudaSuccess) return;
        void* p = nullptr;
        if (cudaGetSymbolAddress(&p, g_ao) != cudaSuccess) return;
        h_ao = (float*)p;

        cudaFuncSetAttribute(flash_tc_kernel,
                             cudaFuncAttributeMaxDynamicSharedMemorySize,
                             FLASH_SMEM);

        dim3 g0(QKVN / 128, M_ / 128);
        dim3 g1(N_ / QT, B_ * H_);
        dim3 g2(C_ / 128, M_ / 128);

        // Warmups: dummy-but-valid fp32 buffers (g_ao fits every role;
        // scratch contents are irrelevant — fully rewritten in real runs).
        gemm_tf32_kernel<0><<<g0, 256>>>(h_ao, h_ao, nullptr, nullptr, C_, QKVN);
        flash_tc_kernel<<<g1, 256, FLASH_SMEM>>>();
        gemm_tf32_kernel<1><<<g2, 256>>>(h_ao, h_ao, h_ao, h_ao, C_, C_);
        if (cudaDeviceSynchronize() != cudaSuccess) return;

        cudaStream_t s = nullptr;
        if (cudaStreamCreate(&s) != cudaSuccess) return;
        cudaGraph_t graph = nullptr;
        cudaGraphExec_t exec = nullptr;
        if (cudaStreamBeginCapture(s, cudaStreamCaptureModeRelaxed) == cudaSuccess) {
            gemm_tf32_kernel<0><<<g0, 256, 0, s>>>(h_ao, h_ao, nullptr, nullptr, C_, QKVN);
            flash_tc_kernel<<<g1, 256, FLASH_SMEM, s>>>();
            gemm_tf32_kernel<1><<<g2, 256, 0, s>>>(h_ao, h_ao, h_ao, h_ao, C_, C_);
            if (cudaStreamEndCapture(s, &graph) == cudaSuccess && graph) {
                if (cudaGraphInstantiate(&exec, graph, nullptr, nullptr, 0) == cudaSuccess && exec) {
                    cudaGraphLaunch(exec, s);
                    cudaStreamSynchronize(s);
                    cudaGraphExecDestroy(exec);
                }
                cudaGraphDestroy(graph);
            }
        }
        cudaStreamDestroy(s);
        cudaDeviceSynchronize();
    }
};
ModulePreloader preloader_;
}

// ---------------------------------------------------------------------------
extern "C" void kernel_launch(void* const* d_in, const int* in_sizes, int n_in,
                              void* d_out, int out_size)
{
    const float* x      = nullptr;   // 6291456
    const float* w_qkv  = nullptr;   // 1769472
    const float* w_proj = nullptr;   // 589824
    const float* b_proj = nullptr;   // 768
    for (int i = 0; i < n_in; i++) {
        switch (in_sizes[i]) {
            case 6291456: x      = (const float*)d_in[i]; break;
            case 1769472: w_qkv  = (const float*)d_in[i]; break;
            case 589824:  w_proj = (const float*)d_in[i]; break;
            case 768:     b_proj = (const float*)d_in[i]; break;
            default: break;
        }
    }
    if (!x)      x      = (const float*)d_in[0];
    if (!w_qkv)  w_qkv  = (const float*)d_in[1];
    if (!w_proj) w_proj = (const float*)d_in[2];
    if (!b_proj) b_proj = (const float*)d_in[3];

    float* out = (float*)d_out;

    if (!h_ao) { void* p; cudaGetSymbolAddress(&p, g_ao); h_ao = (float*)p; }

    // 1) QKV GEMM (tf32) -> fp16 scratch (g_qh/g_kh/g_kl/g_vt)
    {
        dim3 grid(QKVN / 128, M_ / 128);
        gemm_tf32_kernel<0><<<grid, 256>>>(x, w_qkv, nullptr, nullptr, C_, QKVN);
    }
    // 2) Tensor-core flash attention -> g_ao
    {
        dim3 grid(N_ / QT, B_ * H_);
        flash_tc_kernel<<<grid, 256, FLASH_SMEM>>>();
    }
    // 3) Projection GEMM + bias (tf32) -> d_out
    {
        dim3 grid(C_ / 128, M_ / 128);
        gemm_tf32_kernel<1><<<grid, 256>>>(h_ao, w_proj, b_proj, out, C_, C_);
    }
    (void)out_size;
}

// round 11
// speedup vs baseline: 5.8460x; 1.2440x over previous
#include <cuda_runtime.h>
#include <cuda_fp16.h>
#include <cstddef>
#include <cstdint>
#include <math.h>

#define B_  2
#define N_  4096
#define C_  768
#define H_  8
#define DH  96
#define M_  (B_*N_)      // 8192
#define QKVN (3*C_)      // 2304
#define QSCALE 0.1020620726159657f   // 96^-0.5

// Scratch (static __device__ globals)
__device__ __half g_qh[(size_t)M_*C_];        // scale*Q, fp16 [m][768]
__device__ __half g_kh[(size_t)M_*C_];        // K hi fp16 [m][768]
__device__ __half g_kl[(size_t)M_*C_];        // K lo fp16 [m][768]
__device__ __half g_vt[(size_t)B_*H_*DH*N_];  // V^T fp16 [bh][d][n]
__device__ float  g_ao[(size_t)M_*C_];        // attention out fp32 [m][768]

// HOST-side resolved DEVICE address (host-shadow/ATS bug fix from R7).
static float* h_ao = nullptr;

// ---------------------------------------------------------------------------
// fp16 mma helpers
// ---------------------------------------------------------------------------
__device__ __forceinline__ void mma_f16x(float* d, const uint32_t* a, uint32_t b0, uint32_t b1) {
    asm volatile(
        "mma.sync.aligned.m16n8k16.row.col.f32.f16.f16.f32 "
        "{%0,%1,%2,%3}, {%4,%5,%6,%7}, {%8,%9}, {%0,%1,%2,%3};\n"
        : "+f"(d[0]), "+f"(d[1]), "+f"(d[2]), "+f"(d[3])
        : "r"(a[0]), "r"(a[1]), "r"(a[2]), "r"(a[3]), "r"(b0), "r"(b1));
}
__device__ __forceinline__ uint32_t pack_h2(float a, float b) {
    __half2 h = __floats2half2_rn(a, b);
    return *reinterpret_cast<uint32_t*>(&h);
}

// ---------------------------------------------------------------------------
// fp16 tensor-core GEMM: C[M,Nw] = A[M,K] @ B[K,Nw] (+bias if EPI==1).
// fp16 has the SAME 10-bit mantissa as tf32 -> identical precision, 2x rate,
// half the mma count (k16 vs k8). fp32 accumulate.
// CTA tile 128x128, 8 warps (2x4), warp tile 64x32. K-step 16, double-buffer.
// As: [m][8 b32 + pad4] pitch 12 (frag loads hit all 32 banks).
// Bs: [kpair][n] pitch 136 (banks 8*tig+gid -> conflict-free).
// EPI=0 (QKV): epilogue writes fp16 scratch (g_qh scaled / g_kh+g_kl split /
// g_vt transposed); col blocks (128) align with Q/K/V boundaries (768/1536).
// EPI=1 (proj): +bias, fp32 C.
// ---------------------------------------------------------------------------
template<int EPI>
__global__ void __launch_bounds__(256) gemm_f16_kernel(
    const float* __restrict__ A, const float* __restrict__ Bm,
    const float* __restrict__ bias, float* __restrict__ Cout,
    int K, int Nw)
{
    __shared__ uint32_t As[2][128][12];
    __shared__ uint32_t Bs[2][8][136];

    const int t    = threadIdx.x;
    const int lane = t & 31;
    const int wid  = t >> 5;
    const int gid  = lane >> 2;
    const int tig  = lane & 3;
    const int warp_m = wid >> 2;
    const int warp_n = wid & 3;
    const int row0 = blockIdx.y * 128, col0 = blockIdx.x * 128;
    const int m_base = warp_m * 64, n_base = warp_n * 32;

    const int ar  = t >> 1;          // A loader: row 0..127
    const int ak8 = (t & 1);         // A loader: k-offset 0 or 8
    const int bkp = t >> 5;          // B loader: k-pair 0..7
    const int bn  = (t & 31) * 4;    // B loader: n 0..124

    float acc[4][4][4];
    #pragma unroll
    for (int mt = 0; mt < 4; mt++)
        #pragma unroll
        for (int nt = 0; nt < 4; nt++)
            #pragma unroll
            for (int r = 0; r < 4; r++) acc[mt][nt][r] = 0.f;

    const int KSTEPS = K / 16;

    // Prologue: k-tile 0 -> buffer 0
    {
        const float* pa = A + (size_t)(row0 + ar) * K + ak8 * 8;
        float4 f0 = *(const float4*)pa;
        float4 f1 = *(const float4*)(pa + 4);
        *(uint4*)&As[0][ar][ak8 * 4] = make_uint4(
            pack_h2(f0.x, f0.y), pack_h2(f0.z, f0.w),
            pack_h2(f1.x, f1.y), pack_h2(f1.z, f1.w));
        const float* pb0 = Bm + (size_t)(2 * bkp) * Nw + col0 + bn;
        float4 g0 = *(const float4*)pb0;
        float4 g1 = *(const float4*)(pb0 + Nw);
        *(uint4*)&Bs[0][bkp][bn] = make_uint4(
            pack_h2(g0.x, g1.x), pack_h2(g0.y, g1.y),
            pack_h2(g0.z, g1.z), pack_h2(g0.w, g1.w));
    }
    __syncthreads();

    for (int kt = 0; kt < KSTEPS; kt++) {
        const int cur = kt & 1;
        const bool more = (kt + 1 < KSTEPS);
        float4 f0, f1, g0, g1;
        if (more) {
            int k0 = (kt + 1) * 16;
            const float* pa = A + (size_t)(row0 + ar) * K + k0 + ak8 * 8;
            f0 = *(const float4*)pa;
            f1 = *(const float4*)(pa + 4);
            const float* pb0 = Bm + (size_t)(k0 + 2 * bkp) * Nw + col0 + bn;
            g0 = *(const float4*)pb0;
            g1 = *(const float4*)(pb0 + Nw);
        }

        uint32_t bf[4][2];
        #pragma unroll
        for (int nt = 0; nt < 4; nt++) {
            int n = n_base + nt * 8 + gid;
            bf[nt][0] = Bs[cur][tig][n];
            bf[nt][1] = Bs[cur][tig + 4][n];
        }
        #pragma unroll
        for (int mt = 0; mt < 4; mt++) {
            int mb = m_base + mt * 16;
            uint32_t a[4];
            a[0] = As[cur][mb + gid][tig];
            a[1] = As[cur][mb + gid + 8][tig];
            a[2] = As[cur][mb + gid][tig + 4];
            a[3] = As[cur][mb + gid + 8][tig + 4];
            #pragma unroll
            for (int nt = 0; nt < 4; nt++)
                mma_f16x(acc[mt][nt], a, bf[nt][0], bf[nt][1]);
        }

        if (more) {
            *(uint4*)&As[cur ^ 1][ar][ak8 * 4] = make_uint4(
                pack_h2(f0.x, f0.y), pack_h2(f0.z, f0.w),
                pack_h2(f1.x, f1.y), pack_h2(f1.z, f1.w));
            *(uint4*)&Bs[cur ^ 1][bkp][bn] = make_uint4(
                pack_h2(g0.x, g1.x), pack_h2(g0.y, g1.y),
                pack_h2(g0.z, g1.z), pack_h2(g0.w, g1.w));
        }
        __syncthreads();
    }

    #pragma unroll
    for (int mt = 0; mt < 4; mt++) {
        #pragma unroll
        for (int nt = 0; nt < 4; nt++) {
            int r0 = row0 + m_base + mt * 16 + gid;
            int c0 = col0 + n_base + nt * 8 + 2 * tig;
            if (EPI == 1) {
                float bx = bias[c0], by = bias[c0 + 1];
                *(float2*)&Cout[(size_t)r0 * Nw + c0] =
                    make_float2(acc[mt][nt][0] + bx, acc[mt][nt][1] + by);
                *(float2*)&Cout[(size_t)(r0 + 8) * Nw + c0] =
                    make_float2(acc[mt][nt][2] + bx, acc[mt][nt][3] + by);
            } else {
                #pragma unroll
                for (int half_ : {0, 1}) {
                    int m = r0 + half_ * 8;
                    float x = acc[mt][nt][half_ * 2 + 0];
                    float y = acc[mt][nt][half_ * 2 + 1];
                    if (col0 < C_) {                       // Q: scale + fp16
                        *(__half2*)&g_qh[(size_t)m * C_ + c0] =
                            __floats2half2_rn(x * QSCALE, y * QSCALE);
                    } else if (col0 < 2 * C_) {            // K: hi/lo split
                        int ch = c0 - C_;
                        __half hx = __float2half_rn(x), hy = __float2half_rn(y);
                        float rx = x - __half2float(hx), ry = y - __half2float(hy);
                        *(__half2*)&g_kh[(size_t)m * C_ + ch] = __halves2half2(hx, hy);
                        *(__half2*)&g_kl[(size_t)m * C_ + ch] =
                            __halves2half2(__float2half_rn(rx), __float2half_rn(ry));
                    } else {                               // V: fp16, transposed
                        int cv = c0 - 2 * C_;
                        int hh = cv / DH, d = cv - hh * DH;
                        int bb = m >> 12, n = m & (N_ - 1);
                        size_t vbase = ((size_t)(bb * H_ + hh)) * DH;
                        g_vt[(vbase + d) * N_ + n]     = __float2half_rn(x);
                        g_vt[(vbase + d + 1) * N_ + n] = __float2half_rn(y);
                    }
                }
            }
        }
    }
}

// ---------------------------------------------------------------------------
// Tensor-core flash attention.
// Q-tile 128, KV-tile 64, 8 warps (warp w owns q rows w*16..w*16+15).
// S = qh·kh + qh·kl (2x fp16 mma, fp32 accum).
// P stays in REGISTERS: the S-accumulator layout (rows gid/gid+8, cols 2tig)
// is exactly the A-fragment layout for the PV m16n8k16 mma — no smem
// roundtrip, no extra sync. PV fp16 mma, fp32 accum.
// Double-buffered K/V with register-staged uint4 prefetch.
// ---------------------------------------------------------------------------
#define QT 128
#define KT 64
#define QP 52    // b32 pitch for QH/KH/KL rows (96 fp16 = 48 b32 + pad)
#define VP 36    // b32 pitch for VT rows (64 fp16 = 32 b32 + pad)

#define OFF_QH  0
#define OFF_KH0 (OFF_QH + QT*QP)       // 6656
#define OFF_KH1 (OFF_KH0 + KT*QP)      // 9984
#define OFF_KL0 (OFF_KH1 + KT*QP)      // 13312
#define OFF_KL1 (OFF_KL0 + KT*QP)      // 16640
#define OFF_VT0 (OFF_KL1 + KT*QP)      // 19968
#define OFF_VT1 (OFF_VT0 + DH*VP)      // 23424
#define FLASH_SMEM_B32 (OFF_VT1 + DH*VP)    // 26880
#define FLASH_SMEM (FLASH_SMEM_B32 * 4)     // 107520 bytes

__global__ void __launch_bounds__(256) flash_tc_kernel()
{
    extern __shared__ uint32_t su[];
    const int t    = threadIdx.x;
    const int lane = t & 31;
    const int w    = t >> 5;
    const int gid  = lane >> 2;
    const int tig  = lane & 3;
    const int bh = blockIdx.y;
    const int b  = bh >> 3;
    const int h  = bh & 7;
    const int q0 = blockIdx.x * QT;

    const __half* qg = g_qh + ((size_t)b * N_) * C_ + h * DH;   // +n*C_+d
    const __half* kg = g_kh + ((size_t)b * N_) * C_ + h * DH;
    const __half* lg = g_kl + ((size_t)b * N_) * C_ + h * DH;
    const __half* vg = g_vt + ((size_t)bh * DH) * N_;           // +d*N_+n

    // ---- Prologue: Q tile + K/V tile 0 (pure uint4 copies) ----
    #pragma unroll
    for (int i = 0; i < 6; i++) {                  // Q: 128 rows x 12 uint4
        int f = i * 256 + t;
        int row = f / 12, qq = f - row * 12;
        *(uint4*)&su[OFF_QH + row * QP + qq * 4] =
            *(const uint4*)(qg + (size_t)(q0 + row) * C_ + qq * 8);
    }
    #pragma unroll
    for (int i = 0; i < 3; i++) {                  // K hi/lo: 64 rows x 12 uint4
        int f = i * 256 + t;
        int row = f / 12, qq = f - row * 12;
        *(uint4*)&su[OFF_KH0 + row * QP + qq * 4] =
            *(const uint4*)(kg + (size_t)row * C_ + qq * 8);
        *(uint4*)&su[OFF_KL0 + row * QP + qq * 4] =
            *(const uint4*)(lg + (size_t)row * C_ + qq * 8);
    }
    #pragma unroll
    for (int i = 0; i < 3; i++) {                  // V^T: 96 rows x 8 uint4
        int f = i * 256 + t;
        int d = f / 8, nn = f - d * 8;
        *(uint4*)&su[OFF_VT0 + d * VP + nn * 4] =
            *(const uint4*)(vg + (size_t)d * N_ + nn * 8);
    }
    __syncthreads();

    float m0 = -INFINITY, m1 = -INFINITY, l0r = 0.f, l1r = 0.f;
    float o[12][4];
    #pragma unroll
    for (int nt = 0; nt < 12; nt++)
        #pragma unroll
        for (int r = 0; r < 4; r++) o[nt][r] = 0.f;

    const int NTILES = N_ / KT;   // 64
    for (int it = 0; it < NTILES; it++) {
        const int cur = it & 1;
        const bool more = (it + 1 < NTILES);

        // Register-stage next K/V tile (LDGs overlap the mmas below)
        uint4 kst[3], lst[3], vst[3];
        if (more) {
            int k0n = (it + 1) * KT;
            #pragma unroll
            for (int i = 0; i < 3; i++) {
                int f = i * 256 + t;
                int row = f / 12, qq = f - row * 12;
                kst[i] = *(const uint4*)(kg + (size_t)(k0n + row) * C_ + qq * 8);
                lst[i] = *(const uint4*)(lg + (size_t)(k0n + row) * C_ + qq * 8);
            }
            #pragma unroll
            for (int i = 0; i < 3; i++) {
                int f = i * 256 + t;
                int d = f / 8, nn = f - d * 8;
                vst[i] = *(const uint4*)(vg + (size_t)d * N_ + k0n + nn * 8);
            }
        }

        const uint32_t* KH = su + (cur ? OFF_KH1 : OFF_KH0);
        const uint32_t* KL = su + (cur ? OFF_KL1 : OFF_KL0);
        const uint32_t* VT = su + (cur ? OFF_VT1 : OFF_VT0);

        // ---- S = Qs*K^T: 2x fp16 mma per (j,nt), fp32 accum ----
        float s[8][4];
        #pragma unroll
        for (int nt = 0; nt < 8; nt++)
            #pragma unroll
            for (int r = 0; r < 4; r++) s[nt][r] = 0.f;

        #pragma unroll
        for (int j = 0; j < 6; j++) {
            const int qi = (w*16 + gid)*QP + j*8 + tig;
            uint32_t ah[4];
            ah[0] = su[OFF_QH + qi];       ah[1] = su[OFF_QH + qi + 8*QP];
            ah[2] = su[OFF_QH + qi + 4];   ah[3] = su[OFF_QH + qi + 8*QP + 4];
            #pragma unroll
            for (int nt = 0; nt < 8; nt++) {
                const int ki = (nt*8 + gid)*QP + j*8 + tig;
                mma_f16x(s[nt], ah, KH[ki], KH[ki + 4]);
                mma_f16x(s[nt], ah, KL[ki], KL[ki + 4]);
            }
        }

        // ---- Softmax (rows gid, gid+8 of this warp's 16) ----
        float mr0 = -INFINITY, mr1 = -INFINITY;
        #pragma unroll
        for (int nt = 0; nt < 8; nt++) {
            mr0 = fmaxf(mr0, fmaxf(s[nt][0], s[nt][1]));
            mr1 = fmaxf(mr1, fmaxf(s[nt][2], s[nt][3]));
        }
        mr0 = fmaxf(mr0, __shfl_xor_sync(0xffffffffu, mr0, 1));
        mr0 = fmaxf(mr0, __shfl_xor_sync(0xffffffffu, mr0, 2));
        mr1 = fmaxf(mr1, __shfl_xor_sync(0xffffffffu, mr1, 1));
        mr1 = fmaxf(mr1, __shfl_xor_sync(0xffffffffu, mr1, 2));
        const float mn0 = fmaxf(m0, mr0), mn1 = fmaxf(m1, mr1);
        const float sc0 = __expf(m0 - mn0), sc1 = __expf(m1 - mn1);

        // exp -> P directly into PV A-fragments (registers, no smem)
        uint32_t pa[4][4];
        float rs0 = 0.f, rs1 = 0.f;
        #pragma unroll
        for (int nt = 0; nt < 8; nt++) {
            float p00 = __expf(s[nt][0] - mn0);
            float p01 = __expf(s[nt][1] - mn0);
            float p10 = __expf(s[nt][2] - mn1);
            float p11 = __expf(s[nt][3] - mn1);
            rs0 += p00 + p01;
            rs1 += p10 + p11;
            pa[nt >> 1][(nt & 1) * 2 + 0] = pack_h2(p00, p01);
            pa[nt >> 1][(nt & 1) * 2 + 1] = pack_h2(p10, p11);
        }
        rs0 += __shfl_xor_sync(0xffffffffu, rs0, 1);
        rs0 += __shfl_xor_sync(0xffffffffu, rs0, 2);
        rs1 += __shfl_xor_sync(0xffffffffu, rs1, 1);
        rs1 += __shfl_xor_sync(0xffffffffu, rs1, 2);

        l0r = l0r * sc0 + rs0;
        l1r = l1r * sc1 + rs1;
        m0 = mn0; m1 = mn1;

        #pragma unroll
        for (int nt = 0; nt < 12; nt++) {
            o[nt][0] *= sc0; o[nt][1] *= sc0;
            o[nt][2] *= sc1; o[nt][3] *= sc1;
        }

        // ---- O += P @ V (fp16 mma, A-fragments from registers) ----
        #pragma unroll
        for (int jk = 0; jk < 4; jk++) {
            #pragma unroll
            for (int nt = 0; nt < 12; nt++) {
                const int vi = (nt*8 + gid)*VP + jk*8 + tig;
                mma_f16x(o[nt], pa[jk], VT[vi], VT[vi + 4]);
            }
        }

        // ---- Store staged K/V into the other buffer ----
        if (more) {
            uint32_t* KHn = su + (cur ? OFF_KH0 : OFF_KH1);
            uint32_t* KLn = su + (cur ? OFF_KL0 : OFF_KL1);
            uint32_t* VTn = su + (cur ? OFF_VT0 : OFF_VT1);
            #pragma unroll
            for (int i = 0; i < 3; i++) {
                int f = i * 256 + t;
                int row = f / 12, qq = f - row * 12;
                *(uint4*)&KHn[row * QP + qq * 4] = kst[i];
                *(uint4*)&KLn[row * QP + qq * 4] = lst[i];
            }
            #pragma unroll
            for (int i = 0; i < 3; i++) {
                int f = i * 256 + t;
                int d = f / 8, nn = f - d * 8;
                *(uint4*)&VTn[d * VP + nn * 4] = vst[i];
            }
        }
        __syncthreads();
    }

    // ---- Epilogue ----
    const float inv0 = 1.f / l0r, inv1 = 1.f / l1r;
    const size_t orow0 = ((size_t)b * N_ + q0 + w*16 + gid) * C_ + h * DH;
    const size_t orow1 = orow0 + (size_t)8 * C_;
    #pragma unroll
    for (int nt = 0; nt < 12; nt++) {
        *(float2*)(g_ao + orow0 + nt*8 + 2*tig) = make_float2(o[nt][0]*inv0, o[nt][1]*inv0);
        *(float2*)(g_ao + orow1 + nt*8 + 2*tig) = make_float2(o[nt][2]*inv1, o[nt][3]*inv1);
    }
}

// ---------------------------------------------------------------------------
// Static initializer: device addrs, smem attribute, warmups, graph rehearsal.
// ---------------------------------------------------------------------------
namespace {
struct ModulePreloader {
    ModulePreloader() {
        if (cudaFree(0) != cudaSuccess) return;
        void* p = nullptr;
        if (cudaGetSymbolAddress(&p, g_ao) != cudaSuccess) return;
        h_ao = (float*)p;

        cudaFuncSetAttribute(flash_tc_kernel,
                             cudaFuncAttributeMaxDynamicSharedMemorySize,
                             FLASH_SMEM);

        dim3 g0(QKVN / 128, M_ / 128);
        dim3 g1(N_ / QT, B_ * H_);
        dim3 g2(C_ / 128, M_ / 128);

        // Warmups: dummy-but-valid fp32 buffers (g_ao fits every role).
        gemm_f16_kernel<0><<<g0, 256>>>(h_ao, h_ao, nullptr, nullptr, C_, QKVN);
        flash_tc_kernel<<<g1, 256, FLASH_SMEM>>>();
        gemm_f16_kernel<1><<<g2, 256>>>(h_ao, h_ao, h_ao, h_ao, C_, C_);
        if (cudaDeviceSynchronize() != cudaSuccess) return;

        cudaStream_t s = nullptr;
        if (cudaStreamCreate(&s) != cudaSuccess) return;
        cudaGraph_t graph = nullptr;
        cudaGraphExec_t exec = nullptr;
        if (cudaStreamBeginCapture(s, cudaStreamCaptureModeRelaxed) == cudaSuccess) {
            gemm_f16_kernel<0><<<g0, 256, 0, s>>>(h_ao, h_ao, nullptr, nullptr, C_, QKVN);
            flash_tc_kernel<<<g1, 256, FLASH_SMEM, s>>>();
            gemm_f16_kernel<1><<<g2, 256, 0, s>>>(h_ao, h_ao, h_ao, h_ao, C_, C_);
            if (cudaStreamEndCapture(s, &graph) == cudaSuccess && graph) {
                if (cudaGraphInstantiate(&exec, graph, nullptr, nullptr, 0) == cudaSuccess && exec) {
                    cudaGraphLaunch(exec, s);
                    cudaStreamSynchronize(s);
                    cudaGraphExecDestroy(exec);
                }
                cudaGraphDestroy(graph);
            }
        }
        cudaStreamDestroy(s);
        cudaDeviceSynchronize();
    }
};
ModulePreloader preloader_;
}

// ---------------------------------------------------------------------------
extern "C" void kernel_launch(void* const* d_in, const int* in_sizes, int n_in,
                              void* d_out, int out_size)
{
    const float* x      = nullptr;   // 6291456
    const float* w_qkv  = nullptr;   // 1769472
    const float* w_proj = nullptr;   // 589824
    const float* b_proj = nullptr;   // 768
    for (int i = 0; i < n_in; i++) {
        switch (in_sizes[i]) {
            case 6291456: x      = (const float*)d_in[i]; break;
            case 1769472: w_qkv  = (const float*)d_in[i]; break;
            case 589824:  w_proj = (const float*)d_in[i]; break;
            case 768:     b_proj = (const float*)d_in[i]; break;
            default: break;
        }
    }
    if (!x)      x      = (const float*)d_in[0];
    if (!w_qkv)  w_qkv  = (const float*)d_in[1];
    if (!w_proj) w_proj = (const float*)d_in[2];
    if (!b_proj) b_proj = (const float*)d_in[3];

    float* out = (float*)d_out;

    if (!h_ao) { void* p; cudaGetSymbolAddress(&p, g_ao); h_ao = (float*)p; }

    // 1) QKV GEMM (fp16 TC) -> fp16 scratch (g_qh/g_kh/g_kl/g_vt)
    {
        dim3 grid(QKVN / 128, M_ / 128);
        gemm_f16_kernel<0><<<grid, 256>>>(x, w_qkv, nullptr, nullptr, C_, QKVN);
    }
    // 2) Tensor-core flash attention -> g_ao
    {
        dim3 grid(N_ / QT, B_ * H_);
        flash_tc_kernel<<<grid, 256, FLASH_SMEM>>>();
    }
    // 3) Projection GEMM + bias (fp16 TC) -> d_out
    {
        dim3 grid(C_ / 128, M_ / 128);
        gemm_f16_kernel<1><<<grid, 256>>>(h_ao, w_proj, b_proj, out, C_, C_);
    }
    (void)out_size;
}

// round 12
// speedup vs baseline: 7.3394x; 1.2554x over previous
#include <cuda_runtime.h>
#include <cuda_fp16.h>
#include <cstddef>
#include <cstdint>
#include <math.h>

#define B_  2
#define N_  4096
#define C_  768
#define H_  8
#define DH  96
#define M_  (B_*N_)      // 8192
#define QKVN (3*C_)      // 2304
#define QSCALE 0.1020620726159657f   // 96^-0.5

// Scratch (static __device__ globals)
__device__ __half g_qh[(size_t)M_*C_];        // scale*Q, fp16 [m][768]
__device__ __half g_kh[(size_t)M_*C_];        // K fp16 [m][768]
__device__ __half g_vt[(size_t)B_*H_*DH*N_];  // V^T fp16 [bh][d][n]
__device__ float  g_ao[(size_t)M_*C_];        // attention out fp32 [m][768]

// HOST-side resolved DEVICE address (host-shadow/ATS bug fix from R7).
static float* h_ao = nullptr;

// ---------------------------------------------------------------------------
// fp16 mma helpers
// ---------------------------------------------------------------------------
__device__ __forceinline__ void mma_f16x(float* d, const uint32_t* a, uint32_t b0, uint32_t b1) {
    asm volatile(
        "mma.sync.aligned.m16n8k16.row.col.f32.f16.f16.f32 "
        "{%0,%1,%2,%3}, {%4,%5,%6,%7}, {%8,%9}, {%0,%1,%2,%3};\n"
        : "+f"(d[0]), "+f"(d[1]), "+f"(d[2]), "+f"(d[3])
        : "r"(a[0]), "r"(a[1]), "r"(a[2]), "r"(a[3]), "r"(b0), "r"(b1));
}
__device__ __forceinline__ uint32_t pack_h2(float a, float b) {
    __half2 h = __floats2half2_rn(a, b);
    return *reinterpret_cast<uint32_t*>(&h);
}

// ---------------------------------------------------------------------------
// fp16 tensor-core GEMM: C[M,Nw] = A[M,K] @ B[K,Nw] (+bias if EPI==1).
// CTA tile 128x128, 8 warps (2x4), warp tile 64x32. K-step 16, double-buffer.
// EPI=0 (QKV): epilogue writes fp16 scratch (g_qh scaled / g_kh / g_vt
// transposed); 128-col blocks align with Q/K/V boundaries (768/1536).
// EPI=1 (proj): +bias, fp32 C.
// ---------------------------------------------------------------------------
template<int EPI>
__global__ void __launch_bounds__(256) gemm_f16_kernel(
    const float* __restrict__ A, const float* __restrict__ Bm,
    const float* __restrict__ bias, float* __restrict__ Cout,
    int K, int Nw)
{
    __shared__ uint32_t As[2][128][12];
    __shared__ uint32_t Bs[2][8][136];

    const int t    = threadIdx.x;
    const int lane = t & 31;
    const int wid  = t >> 5;
    const int gid  = lane >> 2;
    const int tig  = lane & 3;
    const int warp_m = wid >> 2;
    const int warp_n = wid & 3;
    const int row0 = blockIdx.y * 128, col0 = blockIdx.x * 128;
    const int m_base = warp_m * 64, n_base = warp_n * 32;

    const int ar  = t >> 1;          // A loader: row 0..127
    const int ak8 = (t & 1);         // A loader: k-offset 0 or 8
    const int bkp = t >> 5;          // B loader: k-pair 0..7
    const int bn  = (t & 31) * 4;    // B loader: n 0..124

    float acc[4][4][4];
    #pragma unroll
    for (int mt = 0; mt < 4; mt++)
        #pragma unroll
        for (int nt = 0; nt < 4; nt++)
            #pragma unroll
            for (int r = 0; r < 4; r++) acc[mt][nt][r] = 0.f;

    const int KSTEPS = K / 16;

    {
        const float* pa = A + (size_t)(row0 + ar) * K + ak8 * 8;
        float4 f0 = *(const float4*)pa;
        float4 f1 = *(const float4*)(pa + 4);
        *(uint4*)&As[0][ar][ak8 * 4] = make_uint4(
            pack_h2(f0.x, f0.y), pack_h2(f0.z, f0.w),
            pack_h2(f1.x, f1.y), pack_h2(f1.z, f1.w));
        const float* pb0 = Bm + (size_t)(2 * bkp) * Nw + col0 + bn;
        float4 g0 = *(const float4*)pb0;
        float4 g1 = *(const float4*)(pb0 + Nw);
        *(uint4*)&Bs[0][bkp][bn] = make_uint4(
            pack_h2(g0.x, g1.x), pack_h2(g0.y, g1.y),
            pack_h2(g0.z, g1.z), pack_h2(g0.w, g1.w));
    }
    __syncthreads();

    for (int kt = 0; kt < KSTEPS; kt++) {
        const int cur = kt & 1;
        const bool more = (kt + 1 < KSTEPS);
        float4 f0, f1, g0, g1;
        if (more) {
            int k0 = (kt + 1) * 16;
            const float* pa = A + (size_t)(row0 + ar) * K + k0 + ak8 * 8;
            f0 = *(const float4*)pa;
            f1 = *(const float4*)(pa + 4);
            const float* pb0 = Bm + (size_t)(k0 + 2 * bkp) * Nw + col0 + bn;
            g0 = *(const float4*)pb0;
            g1 = *(const float4*)(pb0 + Nw);
        }

        uint32_t bf[4][2];
        #pragma unroll
        for (int nt = 0; nt < 4; nt++) {
            int n = n_base + nt * 8 + gid;
            bf[nt][0] = Bs[cur][tig][n];
            bf[nt][1] = Bs[cur][tig + 4][n];
        }
        #pragma unroll
        for (int mt = 0; mt < 4; mt++) {
            int mb = m_base + mt * 16;
            uint32_t a[4];
            a[0] = As[cur][mb + gid][tig];
            a[1] = As[cur][mb + gid + 8][tig];
            a[2] = As[cur][mb + gid][tig + 4];
            a[3] = As[cur][mb + gid + 8][tig + 4];
            #pragma unroll
            for (int nt = 0; nt < 4; nt++)
                mma_f16x(acc[mt][nt], a, bf[nt][0], bf[nt][1]);
        }

        if (more) {
            *(uint4*)&As[cur ^ 1][ar][ak8 * 4] = make_uint4(
                pack_h2(f0.x, f0.y), pack_h2(f0.z, f0.w),
                pack_h2(f1.x, f1.y), pack_h2(f1.z, f1.w));
            *(uint4*)&Bs[cur ^ 1][bkp][bn] = make_uint4(
                pack_h2(g0.x, g1.x), pack_h2(g0.y, g1.y),
                pack_h2(g0.z, g1.z), pack_h2(g0.w, g1.w));
        }
        __syncthreads();
    }

    #pragma unroll
    for (int mt = 0; mt < 4; mt++) {
        #pragma unroll
        for (int nt = 0; nt < 4; nt++) {
            int r0 = row0 + m_base + mt * 16 + gid;
            int c0 = col0 + n_base + nt * 8 + 2 * tig;
            if (EPI == 1) {
                float bx = bias[c0], by = bias[c0 + 1];
                *(float2*)&Cout[(size_t)r0 * Nw + c0] =
                    make_float2(acc[mt][nt][0] + bx, acc[mt][nt][1] + by);
                *(float2*)&Cout[(size_t)(r0 + 8) * Nw + c0] =
                    make_float2(acc[mt][nt][2] + bx, acc[mt][nt][3] + by);
            } else {
                #pragma unroll
                for (int half_ : {0, 1}) {
                    int m = r0 + half_ * 8;
                    float x = acc[mt][nt][half_ * 2 + 0];
                    float y = acc[mt][nt][half_ * 2 + 1];
                    if (col0 < C_) {                       // Q: scale + fp16
                        *(__half2*)&g_qh[(size_t)m * C_ + c0] =
                            __floats2half2_rn(x * QSCALE, y * QSCALE);
                    } else if (col0 < 2 * C_) {            // K: fp16
                        int ch = c0 - C_;
                        *(__half2*)&g_kh[(size_t)m * C_ + ch] =
                            __floats2half2_rn(x, y);
                    } else {                               // V: fp16, transposed
                        int cv = c0 - 2 * C_;
                        int hh = cv / DH, d = cv - hh * DH;
                        int bb = m >> 12, n = m & (N_ - 1);
                        size_t vbase = ((size_t)(bb * H_ + hh)) * DH;
                        g_vt[(vbase + d) * N_ + n]     = __float2half_rn(x);
                        g_vt[(vbase + d + 1) * N_ + n] = __float2half_rn(y);
                    }
                }
            }
        }
    }
}

// ---------------------------------------------------------------------------
// Tensor-core flash attention.
// Q-tile 128, KV-tile 64, 8 warps (warp w owns q rows w*16..w*16+15).
// S = qh·kh (1x fp16 mma, fp32 accum). PV fp16 mma, P stays in registers
// (S-accumulator layout == PV A-fragment layout).
// Double-buffered K/V with register-staged uint4 prefetch. smem 81KB.
// ---------------------------------------------------------------------------
#define QT 128
#define KT 64
#define QP 52    // b32 pitch for QH/KH rows (96 fp16 = 48 b32 + pad)
#define VP 36    // b32 pitch for VT rows (64 fp16 = 32 b32 + pad)

#define OFF_QH  0
#define OFF_KH0 (OFF_QH + QT*QP)       // 6656
#define OFF_KH1 (OFF_KH0 + KT*QP)      // 9984
#define OFF_VT0 (OFF_KH1 + KT*QP)      // 13312
#define OFF_VT1 (OFF_VT0 + DH*VP)      // 16768
#define FLASH_SMEM_B32 (OFF_VT1 + DH*VP)    // 20224
#define FLASH_SMEM (FLASH_SMEM_B32 * 4)     // 80896 bytes

__global__ void __launch_bounds__(256) flash_tc_kernel()
{
    extern __shared__ uint32_t su[];
    const int t    = threadIdx.x;
    const int lane = t & 31;
    const int w    = t >> 5;
    const int gid  = lane >> 2;
    const int tig  = lane & 3;
    const int bh = blockIdx.y;
    const int b  = bh >> 3;
    const int h  = bh & 7;
    const int q0 = blockIdx.x * QT;

    const __half* qg = g_qh + ((size_t)b * N_) * C_ + h * DH;   // +n*C_+d
    const __half* kg = g_kh + ((size_t)b * N_) * C_ + h * DH;
    const __half* vg = g_vt + ((size_t)bh * DH) * N_;           // +d*N_+n

    // ---- Prologue: Q tile + K/V tile 0 (pure uint4 copies) ----
    #pragma unroll
    for (int i = 0; i < 6; i++) {                  // Q: 128 rows x 12 uint4
        int f = i * 256 + t;
        int row = f / 12, qq = f - row * 12;
        *(uint4*)&su[OFF_QH + row * QP + qq * 4] =
            *(const uint4*)(qg + (size_t)(q0 + row) * C_ + qq * 8);
    }
    #pragma unroll
    for (int i = 0; i < 3; i++) {                  // K: 64 rows x 12 uint4
        int f = i * 256 + t;
        int row = f / 12, qq = f - row * 12;
        *(uint4*)&su[OFF_KH0 + row * QP + qq * 4] =
            *(const uint4*)(kg + (size_t)row * C_ + qq * 8);
    }
    #pragma unroll
    for (int i = 0; i < 3; i++) {                  // V^T: 96 rows x 8 uint4
        int f = i * 256 + t;
        int d = f / 8, nn = f - d * 8;
        *(uint4*)&su[OFF_VT0 + d * VP + nn * 4] =
            *(const uint4*)(vg + (size_t)d * N_ + nn * 8);
    }
    __syncthreads();

    float m0 = -INFINITY, m1 = -INFINITY, l0r = 0.f, l1r = 0.f;
    float o[12][4];
    #pragma unroll
    for (int nt = 0; nt < 12; nt++)
        #pragma unroll
        for (int r = 0; r < 4; r++) o[nt][r] = 0.f;

    const int NTILES = N_ / KT;   // 64
    for (int it = 0; it < NTILES; it++) {
        const int cur = it & 1;
        const bool more = (it + 1 < NTILES);

        // Register-stage next K/V tile (LDGs overlap the mmas below)
        uint4 kst[3], vst[3];
        if (more) {
            int k0n = (it + 1) * KT;
            #pragma unroll
            for (int i = 0; i < 3; i++) {
                int f = i * 256 + t;
                int row = f / 12, qq = f - row * 12;
                kst[i] = *(const uint4*)(kg + (size_t)(k0n + row) * C_ + qq * 8);
            }
            #pragma unroll
            for (int i = 0; i < 3; i++) {
                int f = i * 256 + t;
                int d = f / 8, nn = f - d * 8;
                vst[i] = *(const uint4*)(vg + (size_t)d * N_ + k0n + nn * 8);
            }
        }

        const uint32_t* KH = su + (cur ? OFF_KH1 : OFF_KH0);
        const uint32_t* VT = su + (cur ? OFF_VT1 : OFF_VT0);

        // ---- S = Qs*K^T: 1x fp16 mma per (j,nt), fp32 accum ----
        float s[8][4];
        #pragma unroll
        for (int nt = 0; nt < 8; nt++)
            #pragma unroll
            for (int r = 0; r < 4; r++) s[nt][r] = 0.f;

        #pragma unroll
        for (int j = 0; j < 6; j++) {
            const int qi = (w*16 + gid)*QP + j*8 + tig;
            uint32_t ah[4];
            ah[0] = su[OFF_QH + qi];       ah[1] = su[OFF_QH + qi + 8*QP];
            ah[2] = su[OFF_QH + qi + 4];   ah[3] = su[OFF_QH + qi + 8*QP + 4];
            #pragma unroll
            for (int nt = 0; nt < 8; nt++) {
                const int ki = (nt*8 + gid)*QP + j*8 + tig;
                mma_f16x(s[nt], ah, KH[ki], KH[ki + 4]);
            }
        }

        // ---- Softmax (rows gid, gid+8 of this warp's 16) ----
        float mr0 = -INFINITY, mr1 = -INFINITY;
        #pragma unroll
        for (int nt = 0; nt < 8; nt++) {
            mr0 = fmaxf(mr0, fmaxf(s[nt][0], s[nt][1]));
            mr1 = fmaxf(mr1, fmaxf(s[nt][2], s[nt][3]));
        }
        mr0 = fmaxf(mr0, __shfl_xor_sync(0xffffffffu, mr0, 1));
        mr0 = fmaxf(mr0, __shfl_xor_sync(0xffffffffu, mr0, 2));
        mr1 = fmaxf(mr1, __shfl_xor_sync(0xffffffffu, mr1, 1));
        mr1 = fmaxf(mr1, __shfl_xor_sync(0xffffffffu, mr1, 2));
        const float mn0 = fmaxf(m0, mr0), mn1 = fmaxf(m1, mr1);
        const float sc0 = __expf(m0 - mn0), sc1 = __expf(m1 - mn1);

        // exp -> P directly into PV A-fragments (registers, no smem)
        uint32_t pa[4][4];
        float rs0 = 0.f, rs1 = 0.f;
        #pragma unroll
        for (int nt = 0; nt < 8; nt++) {
            float p00 = __expf(s[nt][0] - mn0);
            float p01 = __expf(s[nt][1] - mn0);
            float p10 = __expf(s[nt][2] - mn1);
            float p11 = __expf(s[nt][3] - mn1);
            rs0 += p00 + p01;
            rs1 += p10 + p11;
            pa[nt >> 1][(nt & 1) * 2 + 0] = pack_h2(p00, p01);
            pa[nt >> 1][(nt & 1) * 2 + 1] = pack_h2(p10, p11);
        }
        rs0 += __shfl_xor_sync(0xffffffffu, rs0, 1);
        rs0 += __shfl_xor_sync(0xffffffffu, rs0, 2);
        rs1 += __shfl_xor_sync(0xffffffffu, rs1, 1);
        rs1 += __shfl_xor_sync(0xffffffffu, rs1, 2);

        l0r = l0r * sc0 + rs0;
        l1r = l1r * sc1 + rs1;
        m0 = mn0; m1 = mn1;

        #pragma unroll
        for (int nt = 0; nt < 12; nt++) {
            o[nt][0] *= sc0; o[nt][1] *= sc0;
            o[nt][2] *= sc1; o[nt][3] *= sc1;
        }

        // ---- O += P @ V (fp16 mma, A-fragments from registers) ----
        #pragma unroll
        for (int jk = 0; jk < 4; jk++) {
            #pragma unroll
            for (int nt = 0; nt < 12; nt++) {
                const int vi = (nt*8 + gid)*VP + jk*8 + tig;
                mma_f16x(o[nt], pa[jk], VT[vi], VT[vi + 4]);
            }
        }

        // ---- Store staged K/V into the other buffer ----
        if (more) {
            uint32_t* KHn = su + (cur ? OFF_KH0 : OFF_KH1);
            uint32_t* VTn = su + (cur ? OFF_VT0 : OFF_VT1);
            #pragma unroll
            for (int i = 0; i < 3; i++) {
                int f = i * 256 + t;
                int row = f / 12, qq = f - row * 12;
                *(uint4*)&KHn[row * QP + qq * 4] = kst[i];
            }
            #pragma unroll
            for (int i = 0; i < 3; i++) {
                int f = i * 256 + t;
                int d = f / 8, nn = f - d * 8;
                *(uint4*)&VTn[d * VP + nn * 4] = vst[i];
            }
        }
        __syncthreads();
    }

    // ---- Epilogue ----
    const float inv0 = 1.f / l0r, inv1 = 1.f / l1r;
    const size_t orow0 = ((size_t)b * N_ + q0 + w*16 + gid) * C_ + h * DH;
    const size_t orow1 = orow0 + (size_t)8 * C_;
    #pragma unroll
    for (int nt = 0; nt < 12; nt++) {
        *(float2*)(g_ao + orow0 + nt*8 + 2*tig) = make_float2(o[nt][0]*inv0, o[nt][1]*inv0);
        *(float2*)(g_ao + orow1 + nt*8 + 2*tig) = make_float2(o[nt][2]*inv1, o[nt][3]*inv1);
    }
}

// ---------------------------------------------------------------------------
// Static initializer: device addrs, smem attribute, warmups, graph rehearsal.
// ---------------------------------------------------------------------------
namespace {
struct ModulePreloader {
    ModulePreloader() {
        if (cudaFree(0) != cudaSuccess) return;
        void* p = nullptr;
        if (cudaGetSymbolAddress(&p, g_ao) != cudaSuccess) return;
        h_ao = (float*)p;

        cudaFuncSetAttribute(flash_tc_kernel,
                             cudaFuncAttributeMaxDynamicSharedMemorySize,
                             FLASH_SMEM);

        dim3 g0(QKVN / 128, M_ / 128);
        dim3 g1(N_ / QT, B_ * H_);
        dim3 g2(C_ / 128, M_ / 128);

        gemm_f16_kernel<0><<<g0, 256>>>(h_ao, h_ao, nullptr, nullptr, C_, QKVN);
        flash_tc_kernel<<<g1, 256, FLASH_SMEM>>>();
        gemm_f16_kernel<1><<<g2, 256>>>(h_ao, h_ao, h_ao, h_ao, C_, C_);
        if (cudaDeviceSynchronize() != cudaSuccess) return;

        cudaStream_t s = nullptr;
        if (cudaStreamCreate(&s) != cudaSuccess) return;
        cudaGraph_t graph = nullptr;
        cudaGraphExec_t exec = nullptr;
        if (cudaStreamBeginCapture(s, cudaStreamCaptureModeRelaxed) == cudaSuccess) {
            gemm_f16_kernel<0><<<g0, 256, 0, s>>>(h_ao, h_ao, nullptr, nullptr, C_, QKVN);
            flash_tc_kernel<<<g1, 256, FLASH_SMEM, s>>>();
            gemm_f16_kernel<1><<<g2, 256, 0, s>>>(h_ao, h_ao, h_ao, h_ao, C_, C_);
            if (cudaStreamEndCapture(s, &graph) == cudaSuccess && graph) {
                if (cudaGraphInstantiate(&exec, graph, nullptr, nullptr, 0) == cudaSuccess && exec) {
                    cudaGraphLaunch(exec, s);
                    cudaStreamSynchronize(s);
                    cudaGraphExecDestroy(exec);
                }
                cudaGraphDestroy(graph);
            }
        }
        cudaStreamDestroy(s);
        cudaDeviceSynchronize();
    }
};
ModulePreloader preloader_;
}

// ---------------------------------------------------------------------------
extern "C" void kernel_launch(void* const* d_in, const int* in_sizes, int n_in,
                              void* d_out, int out_size)
{
    const float* x      = nullptr;   // 6291456
    const float* w_qkv  = nullptr;   // 1769472
    const float* w_proj = nullptr;   // 589824
    const float* b_proj = nullptr;   // 768
    for (int i = 0; i < n_in; i++) {
        switch (in_sizes[i]) {
            case 6291456: x      = (const float*)d_in[i]; break;
            case 1769472: w_qkv  = (const float*)d_in[i]; break;
            case 589824:  w_proj = (const float*)d_in[i]; break;
            case 768:     b_proj = (const float*)d_in[i]; break;
            default: break;
        }
    }
    if (!x)      x      = (const float*)d_in[0];
    if (!w_qkv)  w_qkv  = (const float*)d_in[1];
    if (!w_proj) w_proj = (const float*)d_in[2];
    if (!b_proj) b_proj = (const float*)d_in[3];

    float* out = (float*)d_out;

    if (!h_ao) { void* p; cudaGetSymbolAddress(&p, g_ao); h_ao = (float*)p; }

    // 1) QKV GEMM (fp16 TC) -> fp16 scratch (g_qh/g_kh/g_vt)
    {
        dim3 grid(QKVN / 128, M_ / 128);
        gemm_f16_kernel<0><<<grid, 256>>>(x, w_qkv, nullptr, nullptr, C_, QKVN);
    }
    // 2) Tensor-core flash attention -> g_ao
    {
        dim3 grid(N_ / QT, B_ * H_);
        flash_tc_kernel<<<grid, 256, FLASH_SMEM>>>();
    }
    // 3) Projection GEMM + bias (fp16 TC) -> d_out
    {
        dim3 grid(C_ / 128, M_ / 128);
        gemm_f16_kernel<1><<<grid, 256>>>(h_ao, w_proj, b_proj, out, C_, C_);
    }
    (void)out_size;
}